// round 8
// baseline (speedup 1.0000x reference)
#include <cuda_runtime.h>
#include <cuda_fp16.h>
#include <cstdint>
#include <math.h>

#define Bb 32
#define Hh 1024
#define Ss 512
#define Tt 32
#define N3 3072
#define NN 6144
#define NCTA 144         // 48 row-tiles x 3 K-splits
#define DSMEM 39552      // B stage 22528 | transpose 16896 | scratch 128

// ===================== helpers =====================
__device__ __forceinline__ uint32_t smem_u32(const void* p) {
    uint32_t a;
    asm("{ .reg .u64 t; cvta.to.shared.u64 t, %1; cvt.u32.u64 %0, t; }" : "=r"(a) : "l"(p));
    return a;
}
__device__ __forceinline__ uint32_t pack_h2(__half x, __half y) {
    return (uint32_t)__half_as_ushort(x) | ((uint32_t)__half_as_ushort(y) << 16);
}
__device__ __forceinline__ float fsigmoid(float x) {
    return 1.f / (1.f + __expf(-x));
}
__device__ __forceinline__ float ftanh(float x) {
    return 2.f / (1.f + __expf(-2.f * x)) - 1.f;
}
// mma.sync m16n8k16 row.col fp16 -> f32
__device__ __forceinline__ void mma16816(float* c, const uint32_t* a, uint32_t b0, uint32_t b1) {
    asm volatile(
        "mma.sync.aligned.m16n8k16.row.col.f32.f16.f16.f32 "
        "{%0,%1,%2,%3}, {%4,%5,%6,%7}, {%8,%9}, {%0,%1,%2,%3};"
        : "+f"(c[0]), "+f"(c[1]), "+f"(c[2]), "+f"(c[3])
        : "r"(a[0]), "r"(a[1]), "r"(a[2]), "r"(a[3]), "r"(b0), "r"(b1));
}
// B-fragment byte offset for element (k=j in [0,1024), n=b): 64 kc blocks of 1KB
__device__ __forceinline__ uint32_t bx_off(int j, int b) {
    int kc = j >> 4, r = j & 15;
    int nn = b >> 3, g = b & 7, t = (r & 7) >> 1;
    return (uint32_t)(kc * 1024 + nn * 256 + (g * 4 + t) * 8 + ((r >= 8) ? 4 : 0) + (r & 1) * 2);
}

// ===================== device scratch =====================
// A fragments over full K: [nt 48][w 8][kc 64][lane 32] uint4
__device__ __align__(128) uint4 g_wfh[786432];    // fp16 hi
__device__ __align__(128) uint4 g_wfl[786432];    // fp16 lo (pre-scaled x4096)
__device__ __align__(128) char g_bx[2][65536];    // B frags fp16: [side x|h][kc 64][nn 4][lane 32] uint2
__device__ __align__(16) float g_yT[(size_t)3 * Bb * NN]; // y partials: [ks][batch][gate]
__device__ __align__(16) float g_a[Bb * Ss];
__device__ __align__(16) float g_v1[Hh];
__device__ __align__(16) float g_v2[Hh];
__device__ __align__(16) float g_bias[NN];
// split barriers: atomic arrivals + store/load release
__device__ unsigned g_ycnt, g_hcnt, g_xcnt;
__device__ volatile unsigned g_yrel, g_hrel, g_xrel;

// ===================== prep kernels =====================
__global__ void prep_wfr(const float* __restrict__ w_ih, const float* __restrict__ w_hh) {
    int idx = blockIdx.x * 256 + threadIdx.x;  // 786432 total
    int lane = idx & 31;
    int kc = (idx >> 5) & 63;
    int w = (idx >> 11) & 7;
    int nt = idx >> 14;
    int g = lane >> 2, t = lane & 3;
    int r0 = nt * 128 + w * 16 + g;
    int r1 = r0 + 8;
    int k0 = kc * 16 + 2 * t;

    float v[8];
    int rows[2] = {r0, r1};
#pragma unroll
    for (int rr = 0; rr < 2; rr++) {
        const float* W = (rows[rr] < N3) ? (w_ih + (size_t)rows[rr] * Hh)
                                         : (w_hh + (size_t)(rows[rr] - N3) * Hh);
        v[rr * 2 + 0] = W[k0];
        v[rr * 2 + 1] = W[k0 + 1];
        v[rr * 2 + 4] = W[k0 + 8];
        v[rr * 2 + 5] = W[k0 + 9];
    }
    uint32_t hi[4], lo[4];
#pragma unroll
    for (int i = 0; i < 4; i++) {
        float a = v[2 * i], b = v[2 * i + 1];
        __half ha = __float2half_rn(a);
        __half hb = __float2half_rn(b);
        __half la = __float2half_rn((a - __half2float(ha)) * 4096.f);
        __half lb = __float2half_rn((b - __half2float(hb)) * 4096.f);
        hi[i] = pack_h2(ha, hb);
        lo[i] = pack_h2(la, lb);
    }
    g_wfh[idx] = make_uint4(hi[0], hi[1], hi[2], hi[3]);
    g_wfl[idx] = make_uint4(lo[0], lo[1], lo[2], lo[3]);
}

// initial B pack: x = features fp16, h = 0; reset barrier state
__global__ void prep_pack_b(const float* __restrict__ features) {
    int b = blockIdx.x, tid = threadIdx.x;
    if (b == 0 && tid == 0) {
        g_ycnt = 0u; g_hcnt = 0u; g_xcnt = 0u;
        g_yrel = 0u; g_hrel = 0u; g_xrel = 0u;
    }
#pragma unroll
    for (int jj = 0; jj < 4; jj++) {
        int j = tid + jj * 256;
        float v = features[b * Hh + j];
        uint32_t off = bx_off(j, b);
        *(unsigned short*)(g_bx[0] + off) = __half_as_ushort(__float2half_rn(v));
        *(unsigned short*)(g_bx[1] + off) = 0;
    }
}

__global__ void prep_v(const float* __restrict__ W1, const float* __restrict__ W2,
                       const float* __restrict__ V) {
    __shared__ float vs[Hh];
    int tid = threadIdx.x;
    for (int i = tid; i < Hh; i += 256) vs[i] = V[i];
    __syncthreads();
    int sel = blockIdx.x >> 2;
    int d = (blockIdx.x & 3) * 256 + tid;
    const float* W = sel ? W2 : W1;
    float acc = 0.f;
    for (int h = 0; h < Hh; h++) acc = fmaf(vs[h], W[(size_t)h * Hh + d], acc);
    if (sel) g_v2[d] = acc; else g_v1[d] = acc;
}

__global__ void prep_bias(const float* __restrict__ b_ih, const float* __restrict__ b_hh) {
    int i = blockIdx.x * 1024 + threadIdx.x;
    g_bias[i] = (i < N3) ? b_ih[i] : b_hh[i - N3];
}

__global__ void prep_a(const float* __restrict__ inputs) {
    __shared__ float v2s[Hh];
    int tid = threadIdx.x;
    for (int i = tid; i < Hh; i += 256) v2s[i] = g_v2[i];
    __syncthreads();
    int warp = tid >> 5, lane = tid & 31;
    int row = blockIdx.x * 8 + warp;
    const float* r = inputs + (size_t)row * Hh;
    float acc = 0.f;
#pragma unroll
    for (int i = 0; i < 8; i++) {
        float4 x4 = *(const float4*)&r[(i * 32 + lane) * 4];
        float4 v4 = *(const float4*)&v2s[(i * 32 + lane) * 4];
        acc += x4.x * v4.x + x4.y * v4.y + x4.z * v4.z + x4.w * v4.w;
    }
#pragma unroll
    for (int o = 16; o > 0; o >>= 1) acc += __shfl_xor_sync(0xFFFFFFFFu, acc, o);
    if (lane == 0) g_a[row] = acc;
}

// ===================== persistent GRU loop =====================
extern __shared__ char dsm[];

__global__ void __launch_bounds__(256, 1)
gru_persist(const float* __restrict__ inputs, const float* __restrict__ mask,
            float* __restrict__ probs) {
    const int c = blockIdx.x;            // 0..143
    const int nt = c / 3;                // row tile 0..47
    const int ks = c - nt * 3;           // K-split 0..2
    const int kc0 = (ks == 0) ? 0 : (ks == 1 ? 22 : 43);
    const int nkc = (ks == 0) ? 22 : 21;
    const int tid = threadIdx.x;
    const int wid = tid >> 5;
    const int lane = tid & 31;
    const int side = (nt >= 24) ? 1 : 0; // 0: x-side rows, 1: h-side rows
    const int b = c;                     // epilogue batch (c < 32 only)
    const bool is_epi = (c < Bb);

    const uint4* Ah = g_wfh + ((size_t)(nt * 8 + wid) * 64) * 32;
    const uint4* Al = g_wfl + ((size_t)(nt * 8 + wid) * 64) * 32;
    const char* bsrc = g_bx[side] + kc0 * 1024;
    const uint32_t sbB = smem_u32(dsm);
    float* smT = (float*)(dsm + 22528);     // 32 cols x 132 floats
    float* red = (float*)(dsm + 39424);
    float* sv  = (float*)(dsm + 39456);
    int*   si  = (int*)(dsm + 39488);

    // ---- hoist epilogue constants ----
    float hreg[4];
    float brr[4], bzz[4], bni[4], bnh[4], v1r[4];
    float areg0 = 0.f, areg1 = 0.f, mk0 = 0.f, mk1 = 0.f;
    if (is_epi) {
#pragma unroll
        for (int k = 0; k < 4; k++) {
            int j = tid + 256 * k;
            hreg[k] = 0.f;
            brr[k] = g_bias[j] + g_bias[3072 + j];
            bzz[k] = g_bias[1024 + j] + g_bias[4096 + j];
            bni[k] = g_bias[2048 + j];
            bnh[k] = g_bias[5120 + j];
            v1r[k] = g_v1[j];
        }
        areg0 = g_a[b * Ss + tid];
        areg1 = g_a[b * Ss + tid + 256];
        mk0 = mask[b * Ss + tid];
        mk1 = mask[b * Ss + tid + 256];
    }

    for (int t = 0; t < Tt; t++) {
        // ---- wait for this side's operand ----
        if (tid == 0) {
            volatile unsigned* rel = side ? &g_hrel : &g_xrel;
            while (*rel < (unsigned)t) { }
            __threadfence();
        }
        __syncthreads();

        // ---- stage B block (nkc KB) into smem via cp.async (L2-coherent) ----
        for (int i = tid; i < nkc * 64; i += 256) {
            asm volatile("cp.async.cg.shared.global [%0], [%1], 16;"
                :: "r"(sbB + i * 16),
                   "l"(__cvta_generic_to_global(bsrc + i * 16)) : "memory");
        }
        asm volatile("cp.async.commit_group;" ::: "memory");
        asm volatile("cp.async.wait_group 0;" ::: "memory");
        __syncthreads();

        // ---- GEMM: 128 rows x 32 batch x K=nkc*16, fp16 2-term split ----
        float acch[4][4], accl[4][4];
#pragma unroll
        for (int i = 0; i < 4; i++)
#pragma unroll
            for (int j = 0; j < 4; j++) { acch[i][j] = 0.f; accl[i][j] = 0.f; }

        uint4 AH[4], AL[4];
#pragma unroll
        for (int p = 0; p < 3; p++) {
            AH[p] = Ah[(kc0 + p) * 32 + lane];
            AL[p] = Al[(kc0 + p) * 32 + lane];
        }
        for (int p = 0; p < nkc; p++) {
            int s = p & 3;
            uint4 ah = AH[s];
            uint4 al = AL[s];
            if (p + 3 < nkc) {
                int q = (p + 3) & 3;
                AH[q] = Ah[(kc0 + p + 3) * 32 + lane];
                AL[q] = Al[(kc0 + p + 3) * 32 + lane];
            }
            const char* bb = dsm + p * 1024 + lane * 8;
#pragma unroll
            for (int nn = 0; nn < 4; nn++) {
                uint2 bv = *(const uint2*)(bb + nn * 256);
                mma16816(acch[nn], &ah.x, bv.x, bv.y);
                mma16816(accl[nn], &al.x, bv.x, bv.y);
            }
        }

        // ---- transpose in smem, then coalesced store: g_yT[ks][batch][gate] ----
        {
            int r0 = wid * 16 + (lane >> 2);
            int c0 = 2 * (lane & 3);
#pragma unroll
            for (int nn = 0; nn < 4; nn++) {
                int col = nn * 8 + c0;
                smT[col * 132 + r0]             = acch[nn][0] + accl[nn][0] * (1.f / 4096.f);
                smT[(col + 1) * 132 + r0]       = acch[nn][1] + accl[nn][1] * (1.f / 4096.f);
                smT[col * 132 + r0 + 8]         = acch[nn][2] + accl[nn][2] * (1.f / 4096.f);
                smT[(col + 1) * 132 + r0 + 8]   = acch[nn][3] + accl[nn][3] * (1.f / 4096.f);
            }
        }
        __syncthreads();
        {
            float* yb = g_yT + (size_t)ks * Bb * NN + nt * 128;
            for (int i = tid; i < 1024; i += 256) {
                int col = i >> 5;
                int r4 = (i & 31) * 4;
                const float* sp = smT + col * 132 + r4;
                float4 v = make_float4(sp[0], sp[1], sp[2], sp[3]);
                *(float4*)(yb + (size_t)col * NN + r4) = v;
            }
        }
        __threadfence();
        __syncthreads();
        if (tid == 0) {
            unsigned prev = atomicAdd(&g_ycnt, 1u);
            if (prev == (unsigned)(NCTA * (t + 1) - 1)) {
                __threadfence();
                g_yrel = (unsigned)(t + 1);
            }
        }

        // ---- epilogue on CTAs 0..31 (batch b) ----
        if (is_epi) {
            if (tid == 0) {
                while (g_yrel < (unsigned)(t + 1)) { }
                __threadfence();
            }
            __syncthreads();

            const float* y0 = g_yT + (size_t)b * NN;
            const float* y1 = g_yT + (size_t)(Bb + b) * NN;
            const float* y2 = g_yT + (size_t)(2 * Bb + b) * NN;

            float yv[6][4];
#pragma unroll
            for (int g = 0; g < 6; g++)
#pragma unroll
                for (int k = 0; k < 4; k++) {
                    int j = g * 1024 + k * 256 + tid;
                    yv[g][k] = y0[j] + y1[j] + y2[j];
                }

            // ---- part A: gates, h update, h repack ----
            float cpart = 0.f;
#pragma unroll
            for (int k = 0; k < 4; k++) {
                int j = tid + 256 * k;
                float r = fsigmoid(yv[0][k] + yv[3][k] + brr[k]);
                float z = fsigmoid(yv[1][k] + yv[4][k] + bzz[k]);
                float nv = ftanh(yv[2][k] + bni[k] + r * (yv[5][k] + bnh[k]));
                float hnew = (1.f - z) * nv + z * hreg[k];
                hreg[k] = hnew;
                *(unsigned short*)(g_bx[1] + bx_off(j, b)) =
                    __half_as_ushort(__float2half_rn(hnew));
                cpart = fmaf(v1r[k], hnew, cpart);
            }
            // release h: h-side GEMM CTAs start next step NOW
            __threadfence();
            __syncthreads();
            if (tid == 0) {
                unsigned prev = atomicAdd(&g_hcnt, 1u);
                if (prev == (unsigned)(Bb * (t + 1) - 1)) {
                    __threadfence();
                    g_hrel = (unsigned)(t + 1);
                }
            }

            // ---- part B: c reduce, scores, argmax, x gather/repack ----
#pragma unroll
            for (int o = 16; o > 0; o >>= 1) cpart += __shfl_xor_sync(0xFFFFFFFFu, cpart, o);
            if (lane == 0) red[wid] = cpart;
            __syncthreads();
            if (wid == 0) {
                float v = (lane < 8) ? red[lane] : 0.f;
#pragma unroll
                for (int o = 4; o > 0; o >>= 1) v += __shfl_xor_sync(0xFFFFFFFFu, v, o);
                if (lane == 0) red[0] = v;
            }
            __syncthreads();
            float c0v = red[0];

            float s0 = ftanh(c0v + areg0);
            float s1 = ftanh(c0v + areg1);
            float* pr = probs + ((size_t)b * Tt + t) * Ss;
            pr[tid] = s0;
            pr[tid + 256] = s1;
            float m0 = s0 + mk0;
            float m1 = s1 + mk1;
            float bv = m0;
            int bi = tid;
            if (m1 > bv) { bv = m1; bi = tid + 256; }
#pragma unroll
            for (int o = 16; o > 0; o >>= 1) {
                float v = __shfl_xor_sync(0xFFFFFFFFu, bv, o);
                int ii = __shfl_xor_sync(0xFFFFFFFFu, bi, o);
                if (v > bv || (v == bv && ii < bi)) { bv = v; bi = ii; }
            }
            if (lane == 0) { sv[wid] = bv; si[wid] = bi; }
            __syncthreads();
            if (wid == 0) {
                float v = (lane < 8) ? sv[lane] : -3.4e38f;
                int ii = (lane < 8) ? si[lane] : (1 << 30);
#pragma unroll
                for (int o = 4; o > 0; o >>= 1) {
                    float v2 = __shfl_xor_sync(0xFFFFFFFFu, v, o);
                    int i2 = __shfl_xor_sync(0xFFFFFFFFu, ii, o);
                    if (v2 > v || (v2 == v && i2 < ii)) { v = v2; ii = i2; }
                }
                if (lane == 0) si[0] = ii;
            }
            __syncthreads();
            int idx = si[0];
            const float* xr = inputs + ((size_t)b * Ss + idx) * Hh;
#pragma unroll
            for (int k = 0; k < 4; k++) {
                int j = tid + 256 * k;
                *(unsigned short*)(g_bx[0] + bx_off(j, b)) =
                    __half_as_ushort(__float2half_rn(xr[j]));
            }
            // release x
            __threadfence();
            __syncthreads();
            if (tid == 0) {
                unsigned prev = atomicAdd(&g_xcnt, 1u);
                if (prev == (unsigned)(Bb * (t + 1) - 1)) {
                    __threadfence();
                    g_xrel = (unsigned)(t + 1);
                }
            }
        }
    }
}

// ===================== context (step-0 softmax) =====================
__global__ void __launch_bounds__(256) ctx_kernel(const float* __restrict__ inputs,
                                                  const float* __restrict__ mask,
                                                  const float* __restrict__ probs,
                                                  float* __restrict__ ctx) {
    const int b = blockIdx.x;
    const int hq = blockIdx.y;
    const int tid = threadIdx.x;
    __shared__ float p[Ss];
    __shared__ float red[256];

    for (int s = tid; s < Ss; s += 256)
        p[s] = probs[(size_t)b * Tt * Ss + s] + mask[b * Ss + s];
    __syncthreads();
    float m = -1e30f;
    for (int s = tid; s < Ss; s += 256) m = fmaxf(m, p[s]);
    red[tid] = m;
    __syncthreads();
    for (int st = 128; st >= 1; st >>= 1) {
        if (tid < st) red[tid] = fmaxf(red[tid], red[tid + st]);
        __syncthreads();
    }
    const float mx = red[0];
    __syncthreads();
    float sm = 0.f;
    for (int s = tid; s < Ss; s += 256) {
        float e = expf(p[s] - mx);
        p[s] = e;
        sm += e;
    }
    red[tid] = sm;
    __syncthreads();
    for (int st = 128; st >= 1; st >>= 1) {
        if (tid < st) red[tid] += red[tid + st];
        __syncthreads();
    }
    const float Z = red[0];
    __syncthreads();
    const int h = hq * 256 + tid;
    float acc = 0.f;
    for (int s = 0; s < Ss; s++)
        acc = fmaf(p[s], inputs[((size_t)b * Ss + s) * Hh + h], acc);
    ctx[b * Hh + h] = acc / Z;
}

// ===================== launch =====================
extern "C" void kernel_launch(void* const* d_in, const int* in_sizes, int n_in,
                              void* d_out, int out_size) {
    const float* inputs   = (const float*)d_in[0];
    const float* mask     = (const float*)d_in[1];
    // d_in[2] = inputs_embeds (unused, use_emb=False)
    const float* features = (const float*)d_in[3];
    const float* w_ih     = (const float*)d_in[4];
    const float* b_ih     = (const float*)d_in[5];
    const float* w_hh     = (const float*)d_in[6];
    const float* b_hh     = (const float*)d_in[7];
    const float* W1       = (const float*)d_in[8];
    const float* W2       = (const float*)d_in[9];
    const float* V        = (const float*)d_in[10];

    float* out   = (float*)d_out;
    float* probs = out;                            // [B, T, S]
    float* ctx   = out + (size_t)Bb * Tt * Ss;     // [B, H]

    cudaFuncSetAttribute(gru_persist, cudaFuncAttributeMaxDynamicSharedMemorySize, DSMEM);

    prep_pack_b<<<Bb, 256>>>(features);
    prep_v<<<8, 256>>>(W1, W2, V);
    prep_wfr<<<3072, 256>>>(w_ih, w_hh);
    prep_bias<<<NN / 1024, 1024>>>(b_ih, b_hh);
    prep_a<<<(Bb * Ss) / 8, 256>>>(inputs);

    gru_persist<<<NCTA, 256, DSMEM>>>(inputs, mask, probs);

    ctx_kernel<<<dim3(Bb, 4), 256>>>(inputs, mask, probs, ctx);
}

// round 9
// speedup vs baseline: 1.1718x; 1.1718x over previous
#include <cuda_runtime.h>
#include <cuda_fp16.h>
#include <cstdint>
#include <math.h>

#define Bb 32
#define Hh 1024
#define Ss 512
#define Tt 32
#define N3 3072
#define NN 6144
#define NCTA 96          // 48 row-tiles x 2 K-splits (K=512 each, static)
#define NKC 32           // kc iterations per split (compile-time!)
#define DSMEM 49792      // B stage 32768 | transpose 16896 | scratch 128

// ===================== helpers =====================
__device__ __forceinline__ uint32_t smem_u32(const void* p) {
    uint32_t a;
    asm("{ .reg .u64 t; cvta.to.shared.u64 t, %1; cvt.u32.u64 %0, t; }" : "=r"(a) : "l"(p));
    return a;
}
__device__ __forceinline__ uint32_t pack_h2(__half x, __half y) {
    return (uint32_t)__half_as_ushort(x) | ((uint32_t)__half_as_ushort(y) << 16);
}
__device__ __forceinline__ float fsigmoid(float x) {
    return 1.f / (1.f + __expf(-x));
}
__device__ __forceinline__ float ftanh(float x) {
    return 2.f / (1.f + __expf(-2.f * x)) - 1.f;
}
// mma.sync m16n8k16 row.col fp16 -> f32
__device__ __forceinline__ void mma16816(float* c, const uint32_t* a, uint32_t b0, uint32_t b1) {
    asm volatile(
        "mma.sync.aligned.m16n8k16.row.col.f32.f16.f16.f32 "
        "{%0,%1,%2,%3}, {%4,%5,%6,%7}, {%8,%9}, {%0,%1,%2,%3};"
        : "+f"(c[0]), "+f"(c[1]), "+f"(c[2]), "+f"(c[3])
        : "r"(a[0]), "r"(a[1]), "r"(a[2]), "r"(a[3]), "r"(b0), "r"(b1));
}
// B-fragment byte offset for element (k=j in [0,1024), n=b): 64 kc blocks of 1KB
__device__ __forceinline__ uint32_t bx_off(int j, int b) {
    int kc = j >> 4, r = j & 15;
    int nn = b >> 3, g = b & 7, t = (r & 7) >> 1;
    return (uint32_t)(kc * 1024 + nn * 256 + (g * 4 + t) * 8 + ((r >= 8) ? 4 : 0) + (r & 1) * 2);
}

// ===================== device scratch =====================
// A fragments over full K: [nt 48][w 8][kc 64][lane 32] uint4
__device__ __align__(128) uint4 g_wfh[786432];    // fp16 hi
__device__ __align__(128) uint4 g_wfl[786432];    // fp16 lo (pre-scaled x4096)
__device__ __align__(128) char g_bx[2][65536];    // B frags fp16: [side x|h][kc 64][nn 4][lane 32] uint2
__device__ __align__(16) float g_yT[(size_t)2 * Bb * NN]; // y partials: [ks][batch][gate]
__device__ __align__(16) float g_a[Bb * Ss];
__device__ __align__(16) float g_v1[Hh];
__device__ __align__(16) float g_v2[Hh];
__device__ __align__(16) float g_bias[NN];
// split barriers: atomic arrivals + store/load release
__device__ unsigned g_ycnt, g_hcnt, g_xcnt;
__device__ volatile unsigned g_yrel, g_hrel, g_xrel;

// ===================== prep kernels =====================
__global__ void prep_wfr(const float* __restrict__ w_ih, const float* __restrict__ w_hh) {
    int idx = blockIdx.x * 256 + threadIdx.x;  // 786432 total
    int lane = idx & 31;
    int kc = (idx >> 5) & 63;
    int w = (idx >> 11) & 7;
    int nt = idx >> 14;
    int g = lane >> 2, t = lane & 3;
    int r0 = nt * 128 + w * 16 + g;
    int r1 = r0 + 8;
    int k0 = kc * 16 + 2 * t;

    float v[8];
    int rows[2] = {r0, r1};
#pragma unroll
    for (int rr = 0; rr < 2; rr++) {
        const float* W = (rows[rr] < N3) ? (w_ih + (size_t)rows[rr] * Hh)
                                         : (w_hh + (size_t)(rows[rr] - N3) * Hh);
        v[rr * 2 + 0] = W[k0];
        v[rr * 2 + 1] = W[k0 + 1];
        v[rr * 2 + 4] = W[k0 + 8];
        v[rr * 2 + 5] = W[k0 + 9];
    }
    uint32_t hi[4], lo[4];
#pragma unroll
    for (int i = 0; i < 4; i++) {
        float a = v[2 * i], b = v[2 * i + 1];
        __half ha = __float2half_rn(a);
        __half hb = __float2half_rn(b);
        __half la = __float2half_rn((a - __half2float(ha)) * 4096.f);
        __half lb = __float2half_rn((b - __half2float(hb)) * 4096.f);
        hi[i] = pack_h2(ha, hb);
        lo[i] = pack_h2(la, lb);
    }
    g_wfh[idx] = make_uint4(hi[0], hi[1], hi[2], hi[3]);
    g_wfl[idx] = make_uint4(lo[0], lo[1], lo[2], lo[3]);
}

// initial B pack: x = features fp16, h = 0; reset barrier state
__global__ void prep_pack_b(const float* __restrict__ features) {
    int b = blockIdx.x, tid = threadIdx.x;
    if (b == 0 && tid == 0) {
        g_ycnt = 0u; g_hcnt = 0u; g_xcnt = 0u;
        g_yrel = 0u; g_hrel = 0u; g_xrel = 0u;
    }
#pragma unroll
    for (int jj = 0; jj < 4; jj++) {
        int j = tid + jj * 256;
        float v = features[b * Hh + j];
        uint32_t off = bx_off(j, b);
        *(unsigned short*)(g_bx[0] + off) = __half_as_ushort(__float2half_rn(v));
        *(unsigned short*)(g_bx[1] + off) = 0;
    }
}

__global__ void prep_v(const float* __restrict__ W1, const float* __restrict__ W2,
                       const float* __restrict__ V) {
    __shared__ float vs[Hh];
    int tid = threadIdx.x;
    for (int i = tid; i < Hh; i += 256) vs[i] = V[i];
    __syncthreads();
    int sel = blockIdx.x >> 2;
    int d = (blockIdx.x & 3) * 256 + tid;
    const float* W = sel ? W2 : W1;
    float acc = 0.f;
    for (int h = 0; h < Hh; h++) acc = fmaf(vs[h], W[(size_t)h * Hh + d], acc);
    if (sel) g_v2[d] = acc; else g_v1[d] = acc;
}

__global__ void prep_bias(const float* __restrict__ b_ih, const float* __restrict__ b_hh) {
    int i = blockIdx.x * 1024 + threadIdx.x;
    g_bias[i] = (i < N3) ? b_ih[i] : b_hh[i - N3];
}

__global__ void prep_a(const float* __restrict__ inputs) {
    __shared__ float v2s[Hh];
    int tid = threadIdx.x;
    for (int i = tid; i < Hh; i += 256) v2s[i] = g_v2[i];
    __syncthreads();
    int warp = tid >> 5, lane = tid & 31;
    int row = blockIdx.x * 8 + warp;
    const float* r = inputs + (size_t)row * Hh;
    float acc = 0.f;
#pragma unroll
    for (int i = 0; i < 8; i++) {
        float4 x4 = *(const float4*)&r[(i * 32 + lane) * 4];
        float4 v4 = *(const float4*)&v2s[(i * 32 + lane) * 4];
        acc += x4.x * v4.x + x4.y * v4.y + x4.z * v4.z + x4.w * v4.w;
    }
#pragma unroll
    for (int o = 16; o > 0; o >>= 1) acc += __shfl_xor_sync(0xFFFFFFFFu, acc, o);
    if (lane == 0) g_a[row] = acc;
}

// ===================== persistent GRU loop =====================
extern __shared__ char dsm[];

__global__ void __launch_bounds__(256, 1)
gru_persist(const float* __restrict__ inputs, const float* __restrict__ mask,
            float* __restrict__ probs) {
    const int c = blockIdx.x;            // 0..95
    const int nt = c >> 1;               // row tile 0..47
    const int ks = c & 1;                // K-split half
    const int kc0 = ks * NKC;
    const int tid = threadIdx.x;
    const int wid = tid >> 5;
    const int lane = tid & 31;
    const int side = (nt >= 24) ? 1 : 0; // 0: x-side rows, 1: h-side rows
    const int b = c;                     // epilogue batch (c < 32 only)
    const bool is_epi = (c < Bb);

    const uint4* Ah = g_wfh + ((size_t)(nt * 8 + wid) * 64 + kc0) * 32;
    const uint4* Al = g_wfl + ((size_t)(nt * 8 + wid) * 64 + kc0) * 32;
    const char* bsrc = g_bx[side] + kc0 * 1024;
    const uint32_t sbB = smem_u32(dsm);
    float* smT = (float*)(dsm + 32768);     // 32 cols x 132 floats
    float* red = (float*)(dsm + 49664);
    float* sv  = (float*)(dsm + 49696);
    int*   si  = (int*)(dsm + 49728);

    // ---- hoist epilogue constants ----
    float hreg[4];
    float brr[4], bzz[4], bni[4], bnh[4], v1r[4];
    float areg0 = 0.f, areg1 = 0.f, mk0 = 0.f, mk1 = 0.f;
    if (is_epi) {
#pragma unroll
        for (int k = 0; k < 4; k++) {
            int j = tid + 256 * k;
            hreg[k] = 0.f;
            brr[k] = g_bias[j] + g_bias[3072 + j];
            bzz[k] = g_bias[1024 + j] + g_bias[4096 + j];
            bni[k] = g_bias[2048 + j];
            bnh[k] = g_bias[5120 + j];
            v1r[k] = g_v1[j];
        }
        areg0 = g_a[b * Ss + tid];
        areg1 = g_a[b * Ss + tid + 256];
        mk0 = mask[b * Ss + tid];
        mk1 = mask[b * Ss + tid + 256];
    }

    for (int t = 0; t < Tt; t++) {
        // ---- wait for this side's operand ----
        if (tid == 0) {
            volatile unsigned* rel = side ? &g_hrel : &g_xrel;
            while (*rel < (unsigned)t) { }
            __threadfence();
        }
        __syncthreads();

        // ---- stage B block (32KB) into smem via cp.async ----
#pragma unroll
        for (int i = 0; i < 8; i++) {
            int idx = tid + i * 256;
            asm volatile("cp.async.cg.shared.global [%0], [%1], 16;"
                :: "r"(sbB + idx * 16),
                   "l"(__cvta_generic_to_global(bsrc + idx * 16)) : "memory");
        }
        asm volatile("cp.async.commit_group;" ::: "memory");
        asm volatile("cp.async.wait_group 0;" ::: "memory");
        __syncthreads();

        // ---- GEMM: 128 rows x 32 batch x K=512, fp16 2-term split, FULLY UNROLLED ----
        float acch[4][4], accl[4][4];
#pragma unroll
        for (int i = 0; i < 4; i++)
#pragma unroll
            for (int j = 0; j < 4; j++) { acch[i][j] = 0.f; accl[i][j] = 0.f; }

        uint4 AH[4], AL[4];
#pragma unroll
        for (int p = 0; p < 3; p++) {
            AH[p] = Ah[p * 32 + lane];
            AL[p] = Al[p * 32 + lane];
        }
#pragma unroll
        for (int p = 0; p < NKC; p++) {
            const int s = p & 3;
            if (p + 3 < NKC) {
                const int q = (p + 3) & 3;
                AH[q] = Ah[(p + 3) * 32 + lane];
                AL[q] = Al[(p + 3) * 32 + lane];
            }
            const char* bb = dsm + p * 1024 + lane * 8;
#pragma unroll
            for (int nn = 0; nn < 4; nn++) {
                uint2 bv = *(const uint2*)(bb + nn * 256);
                mma16816(acch[nn], &AH[s].x, bv.x, bv.y);
                mma16816(accl[nn], &AL[s].x, bv.x, bv.y);
            }
        }

        // ---- transpose in smem, then coalesced store: g_yT[ks][batch][gate] ----
        {
            int r0 = wid * 16 + (lane >> 2);
            int c0 = 2 * (lane & 3);
#pragma unroll
            for (int nn = 0; nn < 4; nn++) {
                int col = nn * 8 + c0;
                smT[col * 132 + r0]           = acch[nn][0] + accl[nn][0] * (1.f / 4096.f);
                smT[(col + 1) * 132 + r0]     = acch[nn][1] + accl[nn][1] * (1.f / 4096.f);
                smT[col * 132 + r0 + 8]       = acch[nn][2] + accl[nn][2] * (1.f / 4096.f);
                smT[(col + 1) * 132 + r0 + 8] = acch[nn][3] + accl[nn][3] * (1.f / 4096.f);
            }
        }
        __syncthreads();
        {
            float* yb = g_yT + (size_t)ks * Bb * NN + nt * 128;
#pragma unroll
            for (int i2 = 0; i2 < 4; i2++) {
                int i = tid + i2 * 256;
                int col = i >> 5;
                int r4 = (i & 31) * 4;
                const float* sp = smT + col * 132 + r4;
                *(float4*)(yb + (size_t)col * NN + r4) = make_float4(sp[0], sp[1], sp[2], sp[3]);
            }
        }
        __threadfence();
        __syncthreads();
        if (tid == 0) {
            unsigned prev = atomicAdd(&g_ycnt, 1u);
            if (prev == (unsigned)(NCTA * (t + 1) - 1)) {
                __threadfence();
                g_yrel = (unsigned)(t + 1);
            }
        }

        // ---- epilogue on CTAs 0..31 (batch b) ----
        if (is_epi) {
            if (tid == 0) {
                while (g_yrel < (unsigned)(t + 1)) { }
                __threadfence();
            }
            __syncthreads();

            const float* y0 = g_yT + (size_t)b * NN;
            const float* y1 = g_yT + (size_t)(Bb + b) * NN;

            float yv[6][4];
#pragma unroll
            for (int g = 0; g < 6; g++)
#pragma unroll
                for (int k = 0; k < 4; k++) {
                    int j = g * 1024 + k * 256 + tid;
                    yv[g][k] = y0[j] + y1[j];
                }

            // ---- part A: gates, h update, h repack ----
            float cpart = 0.f;
#pragma unroll
            for (int k = 0; k < 4; k++) {
                int j = tid + 256 * k;
                float r = fsigmoid(yv[0][k] + yv[3][k] + brr[k]);
                float z = fsigmoid(yv[1][k] + yv[4][k] + bzz[k]);
                float nv = ftanh(yv[2][k] + bni[k] + r * (yv[5][k] + bnh[k]));
                float hnew = (1.f - z) * nv + z * hreg[k];
                hreg[k] = hnew;
                *(unsigned short*)(g_bx[1] + bx_off(j, b)) =
                    __half_as_ushort(__float2half_rn(hnew));
                cpart = fmaf(v1r[k], hnew, cpart);
            }
            // release h: h-side GEMM CTAs start next step NOW
            __threadfence();
            __syncthreads();
            if (tid == 0) {
                unsigned prev = atomicAdd(&g_hcnt, 1u);
                if (prev == (unsigned)(Bb * (t + 1) - 1)) {
                    __threadfence();
                    g_hrel = (unsigned)(t + 1);
                }
            }

            // ---- part B: c reduce, scores, argmax, x gather/repack ----
#pragma unroll
            for (int o = 16; o > 0; o >>= 1) cpart += __shfl_xor_sync(0xFFFFFFFFu, cpart, o);
            if (lane == 0) red[wid] = cpart;
            __syncthreads();
            if (wid == 0) {
                float v = (lane < 8) ? red[lane] : 0.f;
#pragma unroll
                for (int o = 4; o > 0; o >>= 1) v += __shfl_xor_sync(0xFFFFFFFFu, v, o);
                if (lane == 0) red[0] = v;
            }
            __syncthreads();
            float c0v = red[0];

            float s0 = ftanh(c0v + areg0);
            float s1 = ftanh(c0v + areg1);
            float* pr = probs + ((size_t)b * Tt + t) * Ss;
            pr[tid] = s0;
            pr[tid + 256] = s1;
            float m0 = s0 + mk0;
            float m1 = s1 + mk1;
            float bv = m0;
            int bi = tid;
            if (m1 > bv) { bv = m1; bi = tid + 256; }
#pragma unroll
            for (int o = 16; o > 0; o >>= 1) {
                float v = __shfl_xor_sync(0xFFFFFFFFu, bv, o);
                int ii = __shfl_xor_sync(0xFFFFFFFFu, bi, o);
                if (v > bv || (v == bv && ii < bi)) { bv = v; bi = ii; }
            }
            if (lane == 0) { sv[wid] = bv; si[wid] = bi; }
            __syncthreads();
            if (wid == 0) {
                float v = (lane < 8) ? sv[lane] : -3.4e38f;
                int ii = (lane < 8) ? si[lane] : (1 << 30);
#pragma unroll
                for (int o = 4; o > 0; o >>= 1) {
                    float v2 = __shfl_xor_sync(0xFFFFFFFFu, v, o);
                    int i2 = __shfl_xor_sync(0xFFFFFFFFu, ii, o);
                    if (v2 > v || (v2 == v && i2 < ii)) { v = v2; ii = i2; }
                }
                if (lane == 0) si[0] = ii;
            }
            __syncthreads();
            int idx = si[0];
            const float* xr = inputs + ((size_t)b * Ss + idx) * Hh;
#pragma unroll
            for (int k = 0; k < 4; k++) {
                int j = tid + 256 * k;
                *(unsigned short*)(g_bx[0] + bx_off(j, b)) =
                    __half_as_ushort(__float2half_rn(xr[j]));
            }
            // release x
            __threadfence();
            __syncthreads();
            if (tid == 0) {
                unsigned prev = atomicAdd(&g_xcnt, 1u);
                if (prev == (unsigned)(Bb * (t + 1) - 1)) {
                    __threadfence();
                    g_xrel = (unsigned)(t + 1);
                }
            }
        }
    }
}

// ===================== context (step-0 softmax) =====================
__global__ void __launch_bounds__(256) ctx_kernel(const float* __restrict__ inputs,
                                                  const float* __restrict__ mask,
                                                  const float* __restrict__ probs,
                                                  float* __restrict__ ctx) {
    const int b = blockIdx.x;
    const int hq = blockIdx.y;
    const int tid = threadIdx.x;
    __shared__ float p[Ss];
    __shared__ float red[256];

    for (int s = tid; s < Ss; s += 256)
        p[s] = probs[(size_t)b * Tt * Ss + s] + mask[b * Ss + s];
    __syncthreads();
    float m = -1e30f;
    for (int s = tid; s < Ss; s += 256) m = fmaxf(m, p[s]);
    red[tid] = m;
    __syncthreads();
    for (int st = 128; st >= 1; st >>= 1) {
        if (tid < st) red[tid] = fmaxf(red[tid], red[tid + st]);
        __syncthreads();
    }
    const float mx = red[0];
    __syncthreads();
    float sm = 0.f;
    for (int s = tid; s < Ss; s += 256) {
        float e = expf(p[s] - mx);
        p[s] = e;
        sm += e;
    }
    red[tid] = sm;
    __syncthreads();
    for (int st = 128; st >= 1; st >>= 1) {
        if (tid < st) red[tid] += red[tid + st];
        __syncthreads();
    }
    const float Z = red[0];
    __syncthreads();
    const int h = hq * 256 + tid;
    float acc = 0.f;
    for (int s = 0; s < Ss; s++)
        acc = fmaf(p[s], inputs[((size_t)b * Ss + s) * Hh + h], acc);
    ctx[b * Hh + h] = acc / Z;
}

// ===================== launch =====================
extern "C" void kernel_launch(void* const* d_in, const int* in_sizes, int n_in,
                              void* d_out, int out_size) {
    const float* inputs   = (const float*)d_in[0];
    const float* mask     = (const float*)d_in[1];
    // d_in[2] = inputs_embeds (unused, use_emb=False)
    const float* features = (const float*)d_in[3];
    const float* w_ih     = (const float*)d_in[4];
    const float* b_ih     = (const float*)d_in[5];
    const float* w_hh     = (const float*)d_in[6];
    const float* b_hh     = (const float*)d_in[7];
    const float* W1       = (const float*)d_in[8];
    const float* W2       = (const float*)d_in[9];
    const float* V        = (const float*)d_in[10];

    float* out   = (float*)d_out;
    float* probs = out;                            // [B, T, S]
    float* ctx   = out + (size_t)Bb * Tt * Ss;     // [B, H]

    cudaFuncSetAttribute(gru_persist, cudaFuncAttributeMaxDynamicSharedMemorySize, DSMEM);

    prep_pack_b<<<Bb, 256>>>(features);
    prep_v<<<8, 256>>>(W1, W2, V);
    prep_wfr<<<3072, 256>>>(w_ih, w_hh);
    prep_bias<<<NN / 1024, 1024>>>(b_ih, b_hh);
    prep_a<<<(Bb * Ss) / 8, 256>>>(inputs);

    gru_persist<<<NCTA, 256, DSMEM>>>(inputs, mask, probs);

    ctx_kernel<<<dim3(Bb, 4), 256>>>(inputs, mask, probs, ctx);
}

// round 10
// speedup vs baseline: 1.5771x; 1.3459x over previous
#include <cuda_runtime.h>
#include <cuda_fp16.h>
#include <cstdint>
#include <math.h>

#define Bb 32
#define Hh 1024
#define Ss 512
#define Tt 32
#define N3 3072
#define NN 6144
#define NCTA 96          // 24 M-tiles x 4 K-splits (K=256 each)
#define NKC 16           // kc blocks per pass (compile-time)
#define DSMEM 33536      // B stage 16K | transpose 16.9K | scratch

// ===================== helpers =====================
__device__ __forceinline__ uint32_t smem_u32(const void* p) {
    uint32_t a;
    asm("{ .reg .u64 t; cvta.to.shared.u64 t, %1; cvt.u32.u64 %0, t; }" : "=r"(a) : "l"(p));
    return a;
}
__device__ __forceinline__ uint32_t pack_h2(__half x, __half y) {
    return (uint32_t)__half_as_ushort(x) | ((uint32_t)__half_as_ushort(y) << 16);
}
__device__ __forceinline__ float fsigmoid(float x) {
    return 1.f / (1.f + __expf(-x));
}
__device__ __forceinline__ float ftanh(float x) {
    return 2.f / (1.f + __expf(-2.f * x)) - 1.f;
}
__device__ __forceinline__ void mma16816(float* c, const uint32_t* a, uint32_t b0, uint32_t b1) {
    asm volatile(
        "mma.sync.aligned.m16n8k16.row.col.f32.f16.f16.f32 "
        "{%0,%1,%2,%3}, {%4,%5,%6,%7}, {%8,%9}, {%0,%1,%2,%3};"
        : "+f"(c[0]), "+f"(c[1]), "+f"(c[2]), "+f"(c[3])
        : "r"(a[0]), "r"(a[1]), "r"(a[2]), "r"(a[3]), "r"(b0), "r"(b1));
}
// B-fragment byte offset for element (k=j in [0,1024), n=b): 64 kc blocks of 1KB
__device__ __forceinline__ uint32_t bx_off(int j, int b) {
    int kc = j >> 4, r = j & 15;
    int nn = b >> 3, g = b & 7, t = (r & 7) >> 1;
    return (uint32_t)(kc * 1024 + nn * 256 + (g * 4 + t) * 8 + ((r >= 8) ? 4 : 0) + (r & 1) * 2);
}

// ===================== device scratch =====================
__device__ __align__(128) uint4 g_wfh[786432];    // A frags fp16 hi: [nt 48][w 8][kc 64][lane 32]
__device__ __align__(128) uint4 g_wfl[786432];    // A frags fp16 lo (pre-scaled x4096)
__device__ __align__(128) char g_bx[2][65536];    // B frags fp16: [x|h][kc 64][nn 4][lane 32] uint2
__device__ __align__(16) float g_gx[(size_t)4 * Bb * N3]; // gi partials [ks][b][3072]
__device__ __align__(16) float g_gh[(size_t)4 * Bb * N3]; // gh partials [ks][b][3072]
__device__ __align__(16) float g_vp[2][8][Hh];    // v1/v2 partials
__device__ __align__(16) float g_v1[Hh];
__device__ __align__(16) float g_v2[Hh];
__device__ __align__(16) float g_a[Bb * Ss];
__device__ __align__(16) float g_bias[NN];
__device__ int g_mask_nzv[Bb];
__device__ unsigned g_ycnt, g_hcnt, g_xcnt;
__device__ volatile unsigned g_yrel, g_hrel, g_xrel;

// ===================== prep kernels =====================
// pack x=features, h=0; fold bias; per-batch mask-nonzero flag; reset counters
__global__ void prep_pack_b(const float* __restrict__ features,
                            const float* __restrict__ b_ih,
                            const float* __restrict__ b_hh,
                            const float* __restrict__ mask) {
    int b = blockIdx.x, tid = threadIdx.x;
    int lane = tid & 31, wid = tid >> 5;
    if (b == 0 && tid == 0) {
        g_ycnt = 0u; g_hcnt = 0u; g_xcnt = 0u;
        g_yrel = 0u; g_hrel = 0u; g_xrel = 0u;
    }
    // bias
    int bi = b * 256 + tid;
    if (bi < N3) g_bias[bi] = b_ih[bi];
    else if (bi < NN) g_bias[bi] = b_hh[bi - N3];
    // mask flag for batch b
    __shared__ unsigned wnz[8];
    float m0 = mask[b * Ss + tid], m1 = mask[b * Ss + tid + 256];
    unsigned bal = __ballot_sync(0xFFFFFFFFu, (m0 != 0.f) || (m1 != 0.f));
    if (lane == 0) wnz[wid] = bal;
    __syncthreads();
    if (tid == 0) {
        unsigned o = 0;
#pragma unroll
        for (int i = 0; i < 8; i++) o |= wnz[i];
        g_mask_nzv[b] = (o != 0u);
    }
    // pack
#pragma unroll
    for (int jj = 0; jj < 4; jj++) {
        int j = tid + jj * 256;
        float v = features[b * Hh + j];
        uint32_t off = bx_off(j, b);
        *(unsigned short*)(g_bx[0] + off) = __half_as_ushort(__float2half_rn(v));
        *(unsigned short*)(g_bx[1] + off) = 0;
    }
}

// v partials: coalesced row-wise, grid (8 hchunks, 2 sel)
__global__ void prep_v(const float* __restrict__ W1, const float* __restrict__ W2,
                       const float* __restrict__ V) {
    int hc = blockIdx.x, sel = blockIdx.y, tid = threadIdx.x;
    const float* W = sel ? W2 : W1;
    __shared__ float vs[128];
    if (tid < 128) vs[tid] = V[hc * 128 + tid];
    __syncthreads();
    float acc[4] = {0.f, 0.f, 0.f, 0.f};
    for (int h = 0; h < 128; h++) {
        const float* row = W + (size_t)(hc * 128 + h) * Hh;
        float vh = vs[h];
#pragma unroll
        for (int q = 0; q < 4; q++) acc[q] = fmaf(vh, row[tid + q * 256], acc[q]);
    }
#pragma unroll
    for (int q = 0; q < 4; q++) g_vp[sel][hc][tid + q * 256] = acc[q];
}

__global__ void prep_vred() {
    int i = blockIdx.x * 256 + threadIdx.x;  // 0..2047
    int sel = i >> 10, d = i & 1023;
    float s = 0.f;
#pragma unroll
    for (int hc = 0; hc < 8; hc++) s += g_vp[sel][hc][d];
    if (sel) g_v2[d] = s; else g_v1[d] = s;
}

__global__ void prep_wfr(const float* __restrict__ w_ih, const float* __restrict__ w_hh) {
    int idx = blockIdx.x * 256 + threadIdx.x;
    int lane = idx & 31;
    int kc = (idx >> 5) & 63;
    int w = (idx >> 11) & 7;
    int nt = idx >> 14;
    int g = lane >> 2, t = lane & 3;
    int r0 = nt * 128 + w * 16 + g;
    int r1 = r0 + 8;
    int k0 = kc * 16 + 2 * t;

    float v[8];
    int rows[2] = {r0, r1};
#pragma unroll
    for (int rr = 0; rr < 2; rr++) {
        const float* W = (rows[rr] < N3) ? (w_ih + (size_t)rows[rr] * Hh)
                                         : (w_hh + (size_t)(rows[rr] - N3) * Hh);
        v[rr * 2 + 0] = W[k0];
        v[rr * 2 + 1] = W[k0 + 1];
        v[rr * 2 + 4] = W[k0 + 8];
        v[rr * 2 + 5] = W[k0 + 9];
    }
    uint32_t hi[4], lo[4];
#pragma unroll
    for (int i = 0; i < 4; i++) {
        float a = v[2 * i], b = v[2 * i + 1];
        __half ha = __float2half_rn(a);
        __half hb = __float2half_rn(b);
        __half la = __float2half_rn((a - __half2float(ha)) * 4096.f);
        __half lb = __float2half_rn((b - __half2float(hb)) * 4096.f);
        hi[i] = pack_h2(ha, hb);
        lo[i] = pack_h2(la, lb);
    }
    g_wfh[idx] = make_uint4(hi[0], hi[1], hi[2], hi[3]);
    g_wfl[idx] = make_uint4(lo[0], lo[1], lo[2], lo[3]);
}

__global__ void prep_a(const float* __restrict__ inputs) {
    __shared__ float v2s[Hh];
    int tid = threadIdx.x;
    for (int i = tid; i < Hh; i += 256) v2s[i] = g_v2[i];
    __syncthreads();
    int warp = tid >> 5, lane = tid & 31;
    int row = blockIdx.x * 8 + warp;
    const float* r = inputs + (size_t)row * Hh;
    float acc = 0.f;
#pragma unroll
    for (int i = 0; i < 8; i++) {
        float4 x4 = *(const float4*)&r[(i * 32 + lane) * 4];
        float4 v4 = *(const float4*)&v2s[(i * 32 + lane) * 4];
        acc += x4.x * v4.x + x4.y * v4.y + x4.z * v4.z + x4.w * v4.w;
    }
#pragma unroll
    for (int o = 16; o > 0; o >>= 1) acc += __shfl_xor_sync(0xFFFFFFFFu, acc, o);
    if (lane == 0) g_a[row] = acc;
}

// ===================== GEMM pass: 128 rows x 32 batch x K=256 =====================
extern __shared__ char dsm[];

__device__ __forceinline__ void gemm_pass(const uint4* __restrict__ Afh,
                                          const uint4* __restrict__ Afl,
                                          const char* __restrict__ gB,
                                          float* __restrict__ gdst,
                                          int tid, int lane, int wid) {
    uint32_t sbB = smem_u32(dsm);
#pragma unroll
    for (int i = 0; i < 4; i++) {
        int idx = tid + i * 256;
        asm volatile("cp.async.cg.shared.global [%0], [%1], 16;"
            :: "r"(sbB + idx * 16),
               "l"(__cvta_generic_to_global(gB + idx * 16)) : "memory");
    }
    asm volatile("cp.async.commit_group;" ::: "memory");
    asm volatile("cp.async.wait_group 0;" ::: "memory");
    __syncthreads();

    float acch[4][4], accl[4][4];
#pragma unroll
    for (int i = 0; i < 4; i++)
#pragma unroll
        for (int j = 0; j < 4; j++) { acch[i][j] = 0.f; accl[i][j] = 0.f; }

    uint4 AH[4], AL[4];
#pragma unroll
    for (int p = 0; p < 3; p++) { AH[p] = Afh[p * 32 + lane]; AL[p] = Afl[p * 32 + lane]; }
#pragma unroll
    for (int p = 0; p < NKC; p++) {
        const int s = p & 3;
        if (p + 3 < NKC) {
            const int q = (p + 3) & 3;
            AH[q] = Afh[(p + 3) * 32 + lane];
            AL[q] = Afl[(p + 3) * 32 + lane];
        }
        const char* bb = dsm + p * 1024 + lane * 8;
#pragma unroll
        for (int nn = 0; nn < 4; nn++) {
            uint2 bv = *(const uint2*)(bb + nn * 256);
            mma16816(acch[nn], &AH[s].x, bv.x, bv.y);
            mma16816(accl[nn], &AL[s].x, bv.x, bv.y);
        }
    }
    float* smT = (float*)(dsm + 16384);
    int r0 = wid * 16 + (lane >> 2);
    int c0 = 2 * (lane & 3);
#pragma unroll
    for (int nn = 0; nn < 4; nn++) {
        int col = nn * 8 + c0;
        smT[col * 132 + r0]           = acch[nn][0] + accl[nn][0] * (1.f / 4096.f);
        smT[(col + 1) * 132 + r0]     = acch[nn][1] + accl[nn][1] * (1.f / 4096.f);
        smT[col * 132 + r0 + 8]       = acch[nn][2] + accl[nn][2] * (1.f / 4096.f);
        smT[(col + 1) * 132 + r0 + 8] = acch[nn][3] + accl[nn][3] * (1.f / 4096.f);
    }
    __syncthreads();
#pragma unroll
    for (int i2 = 0; i2 < 4; i2++) {
        int i = tid + i2 * 256;
        int col = i >> 5;
        int r4 = (i & 31) * 4;
        const float* sp = smT + col * 132 + r4;
        *(float4*)(gdst + (size_t)col * N3 + r4) = make_float4(sp[0], sp[1], sp[2], sp[3]);
    }
    __syncthreads();
}

// ===================== persistent GRU loop =====================
__global__ void __launch_bounds__(256, 1)
gru_persist(const float* __restrict__ inputs, const float* __restrict__ mask,
            float* __restrict__ probs) {
    const int c = blockIdx.x;            // 0..95
    const int ntl = c >> 2;              // M-tile 0..23
    const int ks = c & 3;                // K-split 0..3
    const int kc0 = ks * NKC;
    const int tid = threadIdx.x;
    const int wid = tid >> 5;
    const int lane = tid & 31;
    const int b = c;                     // epilogue batch (c < 32)
    const bool is_epi = (c < Bb);

    const uint4* AhX = g_wfh + ((size_t)(ntl * 8 + wid) * 64 + kc0) * 32;
    const uint4* AlX = g_wfl + ((size_t)(ntl * 8 + wid) * 64 + kc0) * 32;
    const uint4* AhH = g_wfh + ((size_t)((24 + ntl) * 8 + wid) * 64 + kc0) * 32;
    const uint4* AlH = g_wfl + ((size_t)((24 + ntl) * 8 + wid) * 64 + kc0) * 32;
    const char* bsrcX = g_bx[0] + kc0 * 1024;
    const char* bsrcH = g_bx[1] + kc0 * 1024;
    float* gxdst = g_gx + (size_t)ks * Bb * N3 + ntl * 128;
    float* ghdst = g_gh + (size_t)ks * Bb * N3 + ntl * 128;

    float* red = (float*)(dsm + 33280);
    float* sv  = (float*)(dsm + 33312);
    int*   si  = (int*)(dsm + 33344);
    int*   sfl = (int*)(dsm + 33376);

    // mask-nonzero flag
    if (tid == 0) {
        int nz = 0;
#pragma unroll
        for (int i = 0; i < Bb; i++) nz |= g_mask_nzv[i];
        sfl[0] = nz;
    }
    __syncthreads();
    const bool mask_nz = (sfl[0] != 0);
    __syncthreads();

    // ---- hoist epilogue constants ----
    float hreg[4], gireg[3][4];
    float brr[4], bzz[4], bni[4], bnh[4], v1r[4];
    float areg0 = 0.f, areg1 = 0.f, mk0 = 0.f, mk1 = 0.f;
    if (is_epi) {
#pragma unroll
        for (int k = 0; k < 4; k++) {
            int j = tid + 256 * k;
            hreg[k] = 0.f;
            brr[k] = g_bias[j] + g_bias[3072 + j];
            bzz[k] = g_bias[1024 + j] + g_bias[4096 + j];
            bni[k] = g_bias[2048 + j];
            bnh[k] = g_bias[5120 + j];
            float s = 0.f;
#pragma unroll
            for (int hc = 0; hc < 8; hc++) s += g_vp[0][hc][j];
            v1r[k] = s;
#pragma unroll
            for (int g = 0; g < 3; g++) gireg[g][k] = 0.f;
        }
        areg0 = g_a[b * Ss + tid];
        areg1 = g_a[b * Ss + tid + 256];
        mk0 = mask[b * Ss + tid];
        mk1 = mask[b * Ss + tid + 256];
    }

    for (int t = 0; t < Tt; t++) {
        const bool xpass = (t <= 1) || mask_nz;
        // ---- wait for operands ----
        if (tid == 0) {
            if (xpass && t >= 1) { while (g_xrel < (unsigned)t) { } }
            else                 { while (g_hrel < (unsigned)t) { } }
            __threadfence();
        }
        __syncthreads();

        if (xpass) gemm_pass(AhX, AlX, bsrcX, gxdst, tid, lane, wid);
        gemm_pass(AhH, AlH, bsrcH, ghdst, tid, lane, wid);

        __threadfence();
        __syncthreads();
        if (tid == 0) {
            unsigned prev = atomicAdd(&g_ycnt, 1u);
            if (prev == (unsigned)(NCTA * (t + 1) - 1)) {
                __threadfence();
                g_yrel = (unsigned)(t + 1);
            }
        }

        // ---- epilogue on CTAs 0..31 ----
        if (is_epi) {
            if (tid == 0) {
                while (g_yrel < (unsigned)(t + 1)) { }
                __threadfence();
            }
            __syncthreads();

            float ghv[3][4];
#pragma unroll
            for (int g = 0; g < 3; g++)
#pragma unroll
                for (int k = 0; k < 4; k++) {
                    int j = g * 1024 + k * 256 + tid;
                    float s = 0.f;
#pragma unroll
                    for (int q = 0; q < 4; q++)
                        s += g_gh[((size_t)q * Bb + b) * N3 + j];
                    ghv[g][k] = s;
                }
            if (xpass) {
#pragma unroll
                for (int g = 0; g < 3; g++)
#pragma unroll
                    for (int k = 0; k < 4; k++) {
                        int j = g * 1024 + k * 256 + tid;
                        float s = 0.f;
#pragma unroll
                        for (int q = 0; q < 4; q++)
                            s += g_gx[((size_t)q * Bb + b) * N3 + j];
                        gireg[g][k] = s;
                    }
            }

            // ---- part A: gates, h update, h repack ----
            float cpart = 0.f;
#pragma unroll
            for (int k = 0; k < 4; k++) {
                int j = tid + 256 * k;
                float r = fsigmoid(gireg[0][k] + ghv[0][k] + brr[k]);
                float z = fsigmoid(gireg[1][k] + ghv[1][k] + bzz[k]);
                float nv = ftanh(gireg[2][k] + bni[k] + r * (ghv[2][k] + bnh[k]));
                float hnew = (1.f - z) * nv + z * hreg[k];
                hreg[k] = hnew;
                *(unsigned short*)(g_bx[1] + bx_off(j, b)) =
                    __half_as_ushort(__float2half_rn(hnew));
                cpart = fmaf(v1r[k], hnew, cpart);
            }
            __threadfence();
            __syncthreads();
            if (tid == 0) {
                unsigned prev = atomicAdd(&g_hcnt, 1u);
                if ((prev & 31u) == 31u) {
                    __threadfence();
                    g_hrel = (unsigned)(t + 1);
                }
            }

            // ---- part B: c reduce, scores, (argmax + x gather when needed) ----
#pragma unroll
            for (int o = 16; o > 0; o >>= 1) cpart += __shfl_xor_sync(0xFFFFFFFFu, cpart, o);
            if (lane == 0) red[wid] = cpart;
            __syncthreads();
            if (wid == 0) {
                float v = (lane < 8) ? red[lane] : 0.f;
#pragma unroll
                for (int o = 4; o > 0; o >>= 1) v += __shfl_xor_sync(0xFFFFFFFFu, v, o);
                if (lane == 0) red[0] = v;
            }
            __syncthreads();
            float c0v = red[0];

            float s0 = ftanh(c0v + areg0);
            float s1 = ftanh(c0v + areg1);
            float* pr = probs + ((size_t)b * Tt + t) * Ss;
            pr[tid] = s0;
            pr[tid + 256] = s1;

            if (t == 0 || mask_nz) {
                float m0 = s0 + mk0;
                float m1 = s1 + mk1;
                float bv = m0;
                int bi = tid;
                if (m1 > bv) { bv = m1; bi = tid + 256; }
#pragma unroll
                for (int o = 16; o > 0; o >>= 1) {
                    float v = __shfl_xor_sync(0xFFFFFFFFu, bv, o);
                    int ii = __shfl_xor_sync(0xFFFFFFFFu, bi, o);
                    if (v > bv || (v == bv && ii < bi)) { bv = v; bi = ii; }
                }
                if (lane == 0) { sv[wid] = bv; si[wid] = bi; }
                __syncthreads();
                if (wid == 0) {
                    float v = (lane < 8) ? sv[lane] : -3.4e38f;
                    int ii = (lane < 8) ? si[lane] : (1 << 30);
#pragma unroll
                    for (int o = 4; o > 0; o >>= 1) {
                        float v2 = __shfl_xor_sync(0xFFFFFFFFu, v, o);
                        int i2 = __shfl_xor_sync(0xFFFFFFFFu, ii, o);
                        if (v2 > v || (v2 == v && i2 < ii)) { v = v2; ii = i2; }
                    }
                    if (lane == 0) si[0] = ii;
                }
                __syncthreads();
                int idx = si[0];
                const float* xr = inputs + ((size_t)b * Ss + idx) * Hh;
#pragma unroll
                for (int k = 0; k < 4; k++) {
                    int j = tid + 256 * k;
                    *(unsigned short*)(g_bx[0] + bx_off(j, b)) =
                        __half_as_ushort(__float2half_rn(xr[j]));
                }
                __threadfence();
                __syncthreads();
                if (tid == 0) {
                    unsigned prev = atomicAdd(&g_xcnt, 1u);
                    if ((prev & 31u) == 31u) {
                        __threadfence();
                        g_xrel = (unsigned)(t + 1);
                    }
                }
            }
        }
    }
}

// ===================== context (step-0 softmax) =====================
__global__ void __launch_bounds__(256) ctx_kernel(const float* __restrict__ inputs,
                                                  const float* __restrict__ mask,
                                                  const float* __restrict__ probs,
                                                  float* __restrict__ ctx) {
    const int b = blockIdx.x;
    const int hq = blockIdx.y;
    const int tid = threadIdx.x;
    __shared__ float p[Ss];
    __shared__ float red[256];

    for (int s = tid; s < Ss; s += 256)
        p[s] = probs[(size_t)b * Tt * Ss + s] + mask[b * Ss + s];
    __syncthreads();
    float m = -1e30f;
    for (int s = tid; s < Ss; s += 256) m = fmaxf(m, p[s]);
    red[tid] = m;
    __syncthreads();
    for (int st = 128; st >= 1; st >>= 1) {
        if (tid < st) red[tid] = fmaxf(red[tid], red[tid + st]);
        __syncthreads();
    }
    const float mx = red[0];
    __syncthreads();
    float sm = 0.f;
    for (int s = tid; s < Ss; s += 256) {
        float e = expf(p[s] - mx);
        p[s] = e;
        sm += e;
    }
    red[tid] = sm;
    __syncthreads();
    for (int st = 128; st >= 1; st >>= 1) {
        if (tid < st) red[tid] += red[tid + st];
        __syncthreads();
    }
    const float Z = red[0];
    __syncthreads();
    const int h = hq * 256 + tid;
    float acc = 0.f;
    for (int s = 0; s < Ss; s++)
        acc = fmaf(p[s], inputs[((size_t)b * Ss + s) * Hh + h], acc);
    ctx[b * Hh + h] = acc / Z;
}

// ===================== launch =====================
extern "C" void kernel_launch(void* const* d_in, const int* in_sizes, int n_in,
                              void* d_out, int out_size) {
    const float* inputs   = (const float*)d_in[0];
    const float* mask     = (const float*)d_in[1];
    // d_in[2] = inputs_embeds (unused, use_emb=False)
    const float* features = (const float*)d_in[3];
    const float* w_ih     = (const float*)d_in[4];
    const float* b_ih     = (const float*)d_in[5];
    const float* w_hh     = (const float*)d_in[6];
    const float* b_hh     = (const float*)d_in[7];
    const float* W1       = (const float*)d_in[8];
    const float* W2       = (const float*)d_in[9];
    const float* V        = (const float*)d_in[10];

    float* out   = (float*)d_out;
    float* probs = out;                            // [B, T, S]
    float* ctx   = out + (size_t)Bb * Tt * Ss;     // [B, H]

    cudaFuncSetAttribute(gru_persist, cudaFuncAttributeMaxDynamicSharedMemorySize, DSMEM);

    prep_pack_b<<<Bb, 256>>>(features, b_ih, b_hh, mask);
    prep_v<<<dim3(8, 2), 256>>>(W1, W2, V);
    prep_vred<<<8, 256>>>();
    prep_wfr<<<3072, 256>>>(w_ih, w_hh);
    prep_a<<<(Bb * Ss) / 8, 256>>>(inputs);

    gru_persist<<<NCTA, 256, DSMEM>>>(inputs, mask, probs);

    ctx_kernel<<<dim3(Bb, 4), 256>>>(inputs, mask, probs, ctx);
}

// round 11
// speedup vs baseline: 1.8780x; 1.1908x over previous
#include <cuda_runtime.h>
#include <cuda_fp16.h>
#include <cstdint>
#include <math.h>

#define Bb 32
#define Hh 1024
#define Ss 512
#define Tt 32
#define N3 3072
#define NN 6144
#define NCTA 96          // GEMM CTAs: 24 M-tiles x 4 K-splits (K=256 each)
#define GRID 128         // + 32 aux CTAs (a-precompute + ctx overlap)
#define NKC 16           // kc blocks per pass (compile-time)
#define DSMEM 33536      // B stage 16K | transpose 16.9K | scratch

// ===================== helpers =====================
__device__ __forceinline__ uint32_t smem_u32(const void* p) {
    uint32_t a;
    asm("{ .reg .u64 t; cvta.to.shared.u64 t, %1; cvt.u32.u64 %0, t; }" : "=r"(a) : "l"(p));
    return a;
}
__device__ __forceinline__ uint32_t pack_h2(__half x, __half y) {
    return (uint32_t)__half_as_ushort(x) | ((uint32_t)__half_as_ushort(y) << 16);
}
__device__ __forceinline__ float fsigmoid(float x) {
    return 1.f / (1.f + __expf(-x));
}
__device__ __forceinline__ float ftanh(float x) {
    return 2.f / (1.f + __expf(-2.f * x)) - 1.f;
}
__device__ __forceinline__ void mma16816(float* c, const uint32_t* a, uint32_t b0, uint32_t b1) {
    asm volatile(
        "mma.sync.aligned.m16n8k16.row.col.f32.f16.f16.f32 "
        "{%0,%1,%2,%3}, {%4,%5,%6,%7}, {%8,%9}, {%0,%1,%2,%3};"
        : "+f"(c[0]), "+f"(c[1]), "+f"(c[2]), "+f"(c[3])
        : "r"(a[0]), "r"(a[1]), "r"(a[2]), "r"(a[3]), "r"(b0), "r"(b1));
}
// B-fragment byte offset for element (k=j in [0,1024), n=b): 64 kc blocks of 1KB
__device__ __forceinline__ uint32_t bx_off(int j, int b) {
    int kc = j >> 4, r = j & 15;
    int nn = b >> 3, g = b & 7, t = (r & 7) >> 1;
    return (uint32_t)(kc * 1024 + nn * 256 + (g * 4 + t) * 8 + ((r >= 8) ? 4 : 0) + (r & 1) * 2);
}
// acquire/release primitives
__device__ __forceinline__ unsigned atom_add_acqrel(unsigned* p, unsigned v) {
    unsigned old;
    asm volatile("atom.add.acq_rel.gpu.u32 %0, [%1], %2;" : "=r"(old) : "l"(p), "r"(v) : "memory");
    return old;
}
__device__ __forceinline__ unsigned ld_acquire(unsigned* p) {
    unsigned v;
    asm volatile("ld.acquire.gpu.u32 %0, [%1];" : "=r"(v) : "l"(p) : "memory");
    return v;
}
__device__ __forceinline__ void st_release(unsigned* p, unsigned v) {
    asm volatile("st.release.gpu.u32 [%0], %1;" :: "l"(p), "r"(v) : "memory");
}

// ===================== device scratch =====================
__device__ __align__(128) uint4 g_wfh[786432];    // A frags fp16 hi: [nt 48][w 8][kc 64][lane 32]
__device__ __align__(128) uint4 g_wfl[786432];    // A frags fp16 lo (pre-scaled x4096)
__device__ __align__(128) char g_bx[2][65536];    // B frags fp16: [x|h][kc 64][nn 4][lane 32] uint2
__device__ __align__(16) float g_gx[(size_t)4 * Bb * N3]; // gi partials [ks][b][3072]
__device__ __align__(16) float g_gh[(size_t)4 * Bb * N3]; // gh partials [ks][b][3072]
__device__ __align__(16) float g_vp[2][8][Hh];    // v1/v2 partials
__device__ __align__(16) float g_v1[Hh];
__device__ __align__(16) float g_v2[Hh];
__device__ __align__(16) float g_a[Bb * Ss];
__device__ __align__(16) float g_bias[NN];
__device__ int g_mask_nzv[Bb];
__device__ unsigned g_ycnt, g_hcnt, g_xcnt, g_acnt;
__device__ unsigned g_yrel, g_hrel, g_xrel, g_arel;

// ===================== prep kernels =====================
__global__ void prep_pack_b(const float* __restrict__ features,
                            const float* __restrict__ b_ih,
                            const float* __restrict__ b_hh,
                            const float* __restrict__ mask) {
    int b = blockIdx.x, tid = threadIdx.x;
    int lane = tid & 31, wid = tid >> 5;
    if (b == 0 && tid == 0) {
        g_ycnt = 0u; g_hcnt = 0u; g_xcnt = 0u; g_acnt = 0u;
        g_yrel = 0u; g_hrel = 0u; g_xrel = 0u; g_arel = 0u;
    }
    int bi = b * 256 + tid;
    if (bi < N3) g_bias[bi] = b_ih[bi];
    else if (bi < NN) g_bias[bi] = b_hh[bi - N3];
    __shared__ unsigned wnz[8];
    float m0 = mask[b * Ss + tid], m1 = mask[b * Ss + tid + 256];
    unsigned bal = __ballot_sync(0xFFFFFFFFu, (m0 != 0.f) || (m1 != 0.f));
    if (lane == 0) wnz[wid] = bal;
    __syncthreads();
    if (tid == 0) {
        unsigned o = 0;
#pragma unroll
        for (int i = 0; i < 8; i++) o |= wnz[i];
        g_mask_nzv[b] = (o != 0u);
    }
#pragma unroll
    for (int jj = 0; jj < 4; jj++) {
        int j = tid + jj * 256;
        float v = features[b * Hh + j];
        uint32_t off = bx_off(j, b);
        *(unsigned short*)(g_bx[0] + off) = __half_as_ushort(__float2half_rn(v));
        *(unsigned short*)(g_bx[1] + off) = 0;
    }
}

__global__ void prep_v(const float* __restrict__ W1, const float* __restrict__ W2,
                       const float* __restrict__ V) {
    int hc = blockIdx.x, sel = blockIdx.y, tid = threadIdx.x;
    const float* W = sel ? W2 : W1;
    __shared__ float vs[128];
    if (tid < 128) vs[tid] = V[hc * 128 + tid];
    __syncthreads();
    float acc[4] = {0.f, 0.f, 0.f, 0.f};
    for (int h = 0; h < 128; h++) {
        const float* row = W + (size_t)(hc * 128 + h) * Hh;
        float vh = vs[h];
#pragma unroll
        for (int q = 0; q < 4; q++) acc[q] = fmaf(vh, row[tid + q * 256], acc[q]);
    }
#pragma unroll
    for (int q = 0; q < 4; q++) g_vp[sel][hc][tid + q * 256] = acc[q];
}

__global__ void prep_vred() {
    int i = blockIdx.x * 256 + threadIdx.x;
    int sel = i >> 10, d = i & 1023;
    float s = 0.f;
#pragma unroll
    for (int hc = 0; hc < 8; hc++) s += g_vp[sel][hc][d];
    if (sel) g_v2[d] = s; else g_v1[d] = s;
}

__global__ void prep_wfr(const float* __restrict__ w_ih, const float* __restrict__ w_hh) {
    int idx = blockIdx.x * 256 + threadIdx.x;
    int lane = idx & 31;
    int kc = (idx >> 5) & 63;
    int w = (idx >> 11) & 7;
    int nt = idx >> 14;
    int g = lane >> 2, t = lane & 3;
    int r0 = nt * 128 + w * 16 + g;
    int r1 = r0 + 8;
    int k0 = kc * 16 + 2 * t;

    float v[8];
    int rows[2] = {r0, r1};
#pragma unroll
    for (int rr = 0; rr < 2; rr++) {
        const float* W = (rows[rr] < N3) ? (w_ih + (size_t)rows[rr] * Hh)
                                         : (w_hh + (size_t)(rows[rr] - N3) * Hh);
        v[rr * 2 + 0] = W[k0];
        v[rr * 2 + 1] = W[k0 + 1];
        v[rr * 2 + 4] = W[k0 + 8];
        v[rr * 2 + 5] = W[k0 + 9];
    }
    uint32_t hi[4], lo[4];
#pragma unroll
    for (int i = 0; i < 4; i++) {
        float a = v[2 * i], b = v[2 * i + 1];
        __half ha = __float2half_rn(a);
        __half hb = __float2half_rn(b);
        __half la = __float2half_rn((a - __half2float(ha)) * 4096.f);
        __half lb = __float2half_rn((b - __half2float(hb)) * 4096.f);
        hi[i] = pack_h2(ha, hb);
        lo[i] = pack_h2(la, lb);
    }
    g_wfh[idx] = make_uint4(hi[0], hi[1], hi[2], hi[3]);
    g_wfl[idx] = make_uint4(lo[0], lo[1], lo[2], lo[3]);
}

// ===================== GEMM pass: 128 rows x 32 batch x K=256 =====================
extern __shared__ char dsm[];

template <bool DOLO>
__device__ __forceinline__ void gemm_pass(const uint4* __restrict__ Afh,
                                          const uint4* __restrict__ Afl,
                                          const char* __restrict__ gB,
                                          float* __restrict__ gdst,
                                          int tid, int lane, int wid) {
    uint32_t sbB = smem_u32(dsm);
#pragma unroll
    for (int i = 0; i < 4; i++) {
        int idx = tid + i * 256;
        asm volatile("cp.async.cg.shared.global [%0], [%1], 16;"
            :: "r"(sbB + idx * 16),
               "l"(__cvta_generic_to_global(gB + idx * 16)) : "memory");
    }
    asm volatile("cp.async.commit_group;" ::: "memory");
    asm volatile("cp.async.wait_group 0;" ::: "memory");
    __syncthreads();

    float acch[4][4], accl[4][4];
#pragma unroll
    for (int i = 0; i < 4; i++)
#pragma unroll
        for (int j = 0; j < 4; j++) { acch[i][j] = 0.f; accl[i][j] = 0.f; }

    uint4 AH[4], AL[4];
#pragma unroll
    for (int p = 0; p < 3; p++) {
        AH[p] = Afh[p * 32 + lane];
        if (DOLO) AL[p] = Afl[p * 32 + lane];
    }
#pragma unroll
    for (int p = 0; p < NKC; p++) {
        const int s = p & 3;
        if (p + 3 < NKC) {
            const int q = (p + 3) & 3;
            AH[q] = Afh[(p + 3) * 32 + lane];
            if (DOLO) AL[q] = Afl[(p + 3) * 32 + lane];
        }
        const char* bb = dsm + p * 1024 + lane * 8;
#pragma unroll
        for (int nn = 0; nn < 4; nn++) {
            uint2 bv = *(const uint2*)(bb + nn * 256);
            mma16816(acch[nn], &AH[s].x, bv.x, bv.y);
            if (DOLO) mma16816(accl[nn], &AL[s].x, bv.x, bv.y);
        }
    }
    float* smT = (float*)(dsm + 16384);
    int r0 = wid * 16 + (lane >> 2);
    int c0 = 2 * (lane & 3);
#pragma unroll
    for (int nn = 0; nn < 4; nn++) {
        int col = nn * 8 + c0;
        if (DOLO) {
            smT[col * 132 + r0]           = acch[nn][0] + accl[nn][0] * (1.f / 4096.f);
            smT[(col + 1) * 132 + r0]     = acch[nn][1] + accl[nn][1] * (1.f / 4096.f);
            smT[col * 132 + r0 + 8]       = acch[nn][2] + accl[nn][2] * (1.f / 4096.f);
            smT[(col + 1) * 132 + r0 + 8] = acch[nn][3] + accl[nn][3] * (1.f / 4096.f);
        } else {
            smT[col * 132 + r0]           = acch[nn][0];
            smT[(col + 1) * 132 + r0]     = acch[nn][1];
            smT[col * 132 + r0 + 8]       = acch[nn][2];
            smT[(col + 1) * 132 + r0 + 8] = acch[nn][3];
        }
    }
    __syncthreads();
#pragma unroll
    for (int i2 = 0; i2 < 4; i2++) {
        int i = tid + i2 * 256;
        int col = i >> 5;
        int r4 = (i & 31) * 4;
        const float* sp = smT + col * 132 + r4;
        *(float4*)(gdst + (size_t)col * N3 + r4) = make_float4(sp[0], sp[1], sp[2], sp[3]);
    }
    __syncthreads();
}

// ===================== persistent kernel =====================
__global__ void __launch_bounds__(256, 1)
gru_persist(const float* __restrict__ inputs, const float* __restrict__ mask,
            float* __restrict__ probs, float* __restrict__ ctx) {
    const int c = blockIdx.x;            // 0..127
    const int tid = threadIdx.x;
    const int wid = tid >> 5;
    const int lane = tid & 31;

    // ================= aux CTAs: a-precompute + ctx overlap =================
    if (c >= NCTA) {
        const int b2 = c - NCTA;
        float* v2s = (float*)dsm;                  // 4KB
        for (int i = tid; i < Hh; i += 256) v2s[i] = g_v2[i];
        __syncthreads();
        // a[b2, s] = inputs[b2, s, :] . v2
        for (int rr = 0; rr < 64; rr++) {
            int row = wid * 64 + rr;
            const float* r = inputs + ((size_t)b2 * Ss + row) * Hh;
            float acc = 0.f;
#pragma unroll
            for (int i = 0; i < 8; i++) {
                float4 x4 = *(const float4*)&r[(i * 32 + lane) * 4];
                float4 v4 = *(const float4*)&v2s[(i * 32 + lane) * 4];
                acc += x4.x * v4.x + x4.y * v4.y + x4.z * v4.z + x4.w * v4.w;
            }
#pragma unroll
            for (int o = 16; o > 0; o >>= 1) acc += __shfl_xor_sync(0xFFFFFFFFu, acc, o);
            if (lane == 0) g_a[b2 * Ss + row] = acc;
        }
        __syncthreads();
        if (tid == 0) {
            unsigned prev = atom_add_acqrel(&g_acnt, 1u);
            if (prev == (unsigned)(Bb - 1)) st_release(&g_arel, 1u);
        }
        // wait for step-0 probs (released via xrel at t=0)
        if (tid == 0) { while (ld_acquire(&g_xrel) < 1u) { } }
        __syncthreads();
        // ctx for batch b2: softmax(probs[b2,0,:] + mask) . inputs[b2]
        float* p = (float*)dsm;                    // 2KB
        float* red2 = (float*)(dsm + 2048);        // 1KB
        for (int s = tid; s < Ss; s += 256)
            p[s] = probs[(size_t)b2 * Tt * Ss + s] + mask[b2 * Ss + s];
        __syncthreads();
        float m = fmaxf(p[tid], p[tid + 256]);
#pragma unroll
        for (int o = 16; o > 0; o >>= 1) m = fmaxf(m, __shfl_xor_sync(0xFFFFFFFFu, m, o));
        if (lane == 0) red2[wid] = m;
        __syncthreads();
        if (tid == 0) {
            float mm = red2[0];
#pragma unroll
            for (int i = 1; i < 8; i++) mm = fmaxf(mm, red2[i]);
            red2[8] = mm;
        }
        __syncthreads();
        const float mx = red2[8];
        float sm = __expf(p[tid] - mx) + __expf(p[tid + 256] - mx);
        p[tid] = __expf(p[tid] - mx);
        p[tid + 256] = __expf(p[tid + 256] - mx);
#pragma unroll
        for (int o = 16; o > 0; o >>= 1) sm += __shfl_xor_sync(0xFFFFFFFFu, sm, o);
        if (lane == 0) red2[16 + wid] = sm;
        __syncthreads();
        if (tid == 0) {
            float ss = 0.f;
#pragma unroll
            for (int i = 0; i < 8; i++) ss += red2[16 + i];
            red2[24] = ss;
        }
        __syncthreads();
        const float Z = red2[24];
        float acc[4] = {0.f, 0.f, 0.f, 0.f};
        for (int s = 0; s < Ss; s++) {
            const float* row = inputs + ((size_t)b2 * Ss + s) * Hh;
            float ps = p[s];
#pragma unroll
            for (int q = 0; q < 4; q++) acc[q] = fmaf(ps, row[tid + q * 256], acc[q]);
        }
#pragma unroll
        for (int q = 0; q < 4; q++) ctx[b2 * Hh + tid + q * 256] = acc[q] / Z;
        return;
    }

    // ================= GEMM + epilogue CTAs =================
    const int ntl = c >> 2;              // M-tile 0..23
    const int ks = c & 3;                // K-split 0..3
    const int kc0 = ks * NKC;
    const int b = c;                     // epilogue batch (c < 32)
    const bool is_epi = (c < Bb);

    const uint4* AhX = g_wfh + ((size_t)(ntl * 8 + wid) * 64 + kc0) * 32;
    const uint4* AlX = g_wfl + ((size_t)(ntl * 8 + wid) * 64 + kc0) * 32;
    const uint4* AhH = g_wfh + ((size_t)((24 + ntl) * 8 + wid) * 64 + kc0) * 32;
    const char* bsrcX = g_bx[0] + kc0 * 1024;
    const char* bsrcH = g_bx[1] + kc0 * 1024;
    float* gxdst = g_gx + (size_t)ks * Bb * N3 + ntl * 128;
    float* ghdst = g_gh + (size_t)ks * Bb * N3 + ntl * 128;

    float* red = (float*)(dsm + 33280);
    float* sv  = (float*)(dsm + 33312);
    int*   si  = (int*)(dsm + 33344);
    int*   sfl = (int*)(dsm + 33376);

    if (tid == 0) {
        int nz = 0;
#pragma unroll
        for (int i = 0; i < Bb; i++) nz |= g_mask_nzv[i];
        sfl[0] = nz;
    }
    __syncthreads();
    const bool mask_nz = (sfl[0] != 0);
    __syncthreads();

    // ---- hoist epilogue constants ----
    float hreg[4], gireg[3][4];
    float brr[4], bzz[4], bni[4], bnh[4], v1r[4];
    float areg0 = 0.f, areg1 = 0.f, mk0 = 0.f, mk1 = 0.f;
    if (is_epi) {
#pragma unroll
        for (int k = 0; k < 4; k++) {
            int j = tid + 256 * k;
            hreg[k] = 0.f;
            brr[k] = g_bias[j] + g_bias[3072 + j];
            bzz[k] = g_bias[1024 + j] + g_bias[4096 + j];
            bni[k] = g_bias[2048 + j];
            bnh[k] = g_bias[5120 + j];
            float s = 0.f;
#pragma unroll
            for (int hc = 0; hc < 8; hc++) s += g_vp[0][hc][j];
            v1r[k] = s;
#pragma unroll
            for (int g = 0; g < 3; g++) gireg[g][k] = 0.f;
        }
        mk0 = mask[b * Ss + tid];
        mk1 = mask[b * Ss + tid + 256];
    }

    for (int t = 0; t < Tt; t++) {
        const bool xpass = (t <= 1) || mask_nz;
        const bool hpass = (t >= 1);
        // ---- wait for operands (none needed at t=0: x packed by prep, h skipped) ----
        if (t >= 1) {
            if (tid == 0) {
                if (xpass) { while (ld_acquire(&g_xrel) < (unsigned)t) { } }
                else       { while (ld_acquire(&g_hrel) < (unsigned)t) { } }
            }
            __syncthreads();
        }

        if (xpass) gemm_pass<true>(AhX, AlX, bsrcX, gxdst, tid, lane, wid);
        if (hpass) gemm_pass<false>(AhH, AhH, bsrcH, ghdst, tid, lane, wid);

        __syncthreads();
        if (tid == 0) {
            unsigned prev = atom_add_acqrel(&g_ycnt, 1u);
            if (prev == (unsigned)(NCTA * (t + 1) - 1)) st_release(&g_yrel, (unsigned)(t + 1));
        }

        // ---- epilogue on CTAs 0..31 ----
        if (is_epi) {
            if (tid == 0) { while (ld_acquire(&g_yrel) < (unsigned)(t + 1)) { } }
            __syncthreads();

            float ghv[3][4];
            if (hpass) {
#pragma unroll
                for (int g = 0; g < 3; g++)
#pragma unroll
                    for (int k = 0; k < 4; k++) {
                        int j = g * 1024 + k * 256 + tid;
                        float s = 0.f;
#pragma unroll
                        for (int q = 0; q < 4; q++)
                            s += g_gh[((size_t)q * Bb + b) * N3 + j];
                        ghv[g][k] = s;
                    }
            } else {
#pragma unroll
                for (int g = 0; g < 3; g++)
#pragma unroll
                    for (int k = 0; k < 4; k++) ghv[g][k] = 0.f;
            }
            if (xpass) {
#pragma unroll
                for (int g = 0; g < 3; g++)
#pragma unroll
                    for (int k = 0; k < 4; k++) {
                        int j = g * 1024 + k * 256 + tid;
                        float s = 0.f;
#pragma unroll
                        for (int q = 0; q < 4; q++)
                            s += g_gx[((size_t)q * Bb + b) * N3 + j];
                        gireg[g][k] = s;
                    }
            }

            // ---- part A: gates, h update, h repack ----
            float cpart = 0.f;
#pragma unroll
            for (int k = 0; k < 4; k++) {
                int j = tid + 256 * k;
                float r = fsigmoid(gireg[0][k] + ghv[0][k] + brr[k]);
                float z = fsigmoid(gireg[1][k] + ghv[1][k] + bzz[k]);
                float nv = ftanh(gireg[2][k] + bni[k] + r * (ghv[2][k] + bnh[k]));
                float hnew = (1.f - z) * nv + z * hreg[k];
                hreg[k] = hnew;
                *(unsigned short*)(g_bx[1] + bx_off(j, b)) =
                    __half_as_ushort(__float2half_rn(hnew));
                cpart = fmaf(v1r[k], hnew, cpart);
            }
            __syncthreads();
            if (tid == 0) {
                unsigned prev = atom_add_acqrel(&g_hcnt, 1u);
                if ((prev & 31u) == 31u) st_release(&g_hrel, (unsigned)(t + 1));
            }

            // ---- part B: c reduce, scores, (argmax + x gather when needed) ----
#pragma unroll
            for (int o = 16; o > 0; o >>= 1) cpart += __shfl_xor_sync(0xFFFFFFFFu, cpart, o);
            if (lane == 0) red[wid] = cpart;
            __syncthreads();
            if (wid == 0) {
                float v = (lane < 8) ? red[lane] : 0.f;
#pragma unroll
                for (int o = 4; o > 0; o >>= 1) v += __shfl_xor_sync(0xFFFFFFFFu, v, o);
                if (lane == 0) red[0] = v;
            }
            __syncthreads();
            float c0v = red[0];

            if (t == 0) {
                // a-values computed by aux CTAs — wait, then load
                if (tid == 0) { while (ld_acquire(&g_arel) == 0u) { } }
                __syncthreads();
                areg0 = g_a[b * Ss + tid];
                areg1 = g_a[b * Ss + tid + 256];
            }

            float s0 = ftanh(c0v + areg0);
            float s1 = ftanh(c0v + areg1);
            float* pr = probs + ((size_t)b * Tt + t) * Ss;
            pr[tid] = s0;
            pr[tid + 256] = s1;

            if (t == 0 || mask_nz) {
                float m0 = s0 + mk0;
                float m1 = s1 + mk1;
                float bv = m0;
                int bi = tid;
                if (m1 > bv) { bv = m1; bi = tid + 256; }
#pragma unroll
                for (int o = 16; o > 0; o >>= 1) {
                    float v = __shfl_xor_sync(0xFFFFFFFFu, bv, o);
                    int ii = __shfl_xor_sync(0xFFFFFFFFu, bi, o);
                    if (v > bv || (v == bv && ii < bi)) { bv = v; bi = ii; }
                }
                if (lane == 0) { sv[wid] = bv; si[wid] = bi; }
                __syncthreads();
                if (wid == 0) {
                    float v = (lane < 8) ? sv[lane] : -3.4e38f;
                    int ii = (lane < 8) ? si[lane] : (1 << 30);
#pragma unroll
                    for (int o = 4; o > 0; o >>= 1) {
                        float v2 = __shfl_xor_sync(0xFFFFFFFFu, v, o);
                        int i2 = __shfl_xor_sync(0xFFFFFFFFu, ii, o);
                        if (v2 > v || (v2 == v && i2 < ii)) { v = v2; ii = i2; }
                    }
                    if (lane == 0) si[0] = ii;
                }
                __syncthreads();
                int idx = si[0];
                const float* xr = inputs + ((size_t)b * Ss + idx) * Hh;
#pragma unroll
                for (int k = 0; k < 4; k++) {
                    int j = tid + 256 * k;
                    *(unsigned short*)(g_bx[0] + bx_off(j, b)) =
                        __half_as_ushort(__float2half_rn(xr[j]));
                }
                __syncthreads();
                if (tid == 0) {
                    unsigned prev = atom_add_acqrel(&g_xcnt, 1u);
                    if ((prev & 31u) == 31u) st_release(&g_xrel, (unsigned)(t + 1));
                }
            }
        }
    }
}

// ===================== launch =====================
extern "C" void kernel_launch(void* const* d_in, const int* in_sizes, int n_in,
                              void* d_out, int out_size) {
    const float* inputs   = (const float*)d_in[0];
    const float* mask     = (const float*)d_in[1];
    // d_in[2] = inputs_embeds (unused, use_emb=False)
    const float* features = (const float*)d_in[3];
    const float* w_ih     = (const float*)d_in[4];
    const float* b_ih     = (const float*)d_in[5];
    const float* w_hh     = (const float*)d_in[6];
    const float* b_hh     = (const float*)d_in[7];
    const float* W1       = (const float*)d_in[8];
    const float* W2       = (const float*)d_in[9];
    const float* V        = (const float*)d_in[10];

    float* out   = (float*)d_out;
    float* probs = out;                            // [B, T, S]
    float* ctx   = out + (size_t)Bb * Tt * Ss;     // [B, H]

    cudaFuncSetAttribute(gru_persist, cudaFuncAttributeMaxDynamicSharedMemorySize, DSMEM);

    prep_pack_b<<<Bb, 256>>>(features, b_ih, b_hh, mask);
    prep_v<<<dim3(8, 2), 256>>>(W1, W2, V);
    prep_vred<<<8, 256>>>();
    prep_wfr<<<3072, 256>>>(w_ih, w_hh);

    gru_persist<<<GRID, 256, DSMEM>>>(inputs, mask, probs, ctx);
}

// round 12
// speedup vs baseline: 1.8899x; 1.0063x over previous
#include <cuda_runtime.h>
#include <cuda_fp16.h>
#include <cstdint>
#include <math.h>

#define Bb 32
#define Hh 1024
#define Ss 512
#define Tt 32
#define N3 3072
#define NN 6144
#define NGEMM 32
#define GRID 64
#define THREADS 384

// smem layout (GEMM CTAs)
#define SM_B 0            // 65536: B stage (fp16 frags, full K)
#define SM_Y0 65536       // 12288: y partial K-half 0 [96][32] f32
#define SM_Y1 78080       // 12288 (pad +256)
#define SM_GX 90624       // 12288: cached gi [96][32] f32
#define SM_HOLD 103168    // 4096: hold h [32][32]
#define SM_BIAS 107264    // 640: br,bz,bni,bnh,v1 x32
#define SM_C32 108032     // 128
#define SM_FLG 108160
#define DSMEM 108288

// ===================== helpers =====================
__device__ __forceinline__ uint32_t smem_u32(const void* p) {
    uint32_t a;
    asm("{ .reg .u64 t; cvta.to.shared.u64 t, %1; cvt.u32.u64 %0, t; }" : "=r"(a) : "l"(p));
    return a;
}
__device__ __forceinline__ uint32_t pack_h2(__half x, __half y) {
    return (uint32_t)__half_as_ushort(x) | ((uint32_t)__half_as_ushort(y) << 16);
}
__device__ __forceinline__ float fsigmoid(float x) { return 1.f / (1.f + __expf(-x)); }
__device__ __forceinline__ float ftanh(float x) { return 2.f / (1.f + __expf(-2.f * x)) - 1.f; }
__device__ __forceinline__ void mma16816(float* c, const uint32_t* a, uint32_t b0, uint32_t b1) {
    asm volatile(
        "mma.sync.aligned.m16n8k16.row.col.f32.f16.f16.f32 "
        "{%0,%1,%2,%3}, {%4,%5,%6,%7}, {%8,%9}, {%0,%1,%2,%3};"
        : "+f"(c[0]), "+f"(c[1]), "+f"(c[2]), "+f"(c[3])
        : "r"(a[0]), "r"(a[1]), "r"(a[2]), "r"(a[3]), "r"(b0), "r"(b1));
}
// B-fragment byte offset for (k=j in [0,1024), n=b)
__device__ __forceinline__ uint32_t bx_off(int j, int b) {
    int kc = j >> 4, r = j & 15;
    int nn = b >> 3, g = b & 7, t = (r & 7) >> 1;
    return (uint32_t)(kc * 1024 + nn * 256 + (g * 4 + t) * 8 + ((r >= 8) ? 4 : 0) + (r & 1) * 2);
}
__device__ __forceinline__ unsigned atom_add_acqrel(unsigned* p, unsigned v) {
    unsigned old;
    asm volatile("atom.add.acq_rel.gpu.u32 %0, [%1], %2;" : "=r"(old) : "l"(p), "r"(v) : "memory");
    return old;
}
__device__ __forceinline__ unsigned ld_acquire(unsigned* p) {
    unsigned v;
    asm volatile("ld.acquire.gpu.u32 %0, [%1];" : "=r"(v) : "l"(p) : "memory");
    return v;
}
__device__ __forceinline__ void st_release(unsigned* p, unsigned v) {
    asm volatile("st.release.gpu.u32 [%0], %1;" :: "l"(p), "r"(v) : "memory");
}

// ===================== device scratch =====================
// A fragments: [m 32][wid 12][kc 32][lane 32] uint4 ; rows permuted into gate-triples
__device__ __align__(128) uint4 g_axh[393216];   // w_ih fp16 hi
__device__ __align__(128) uint4 g_axl[393216];   // w_ih fp16 lo (x4096)
__device__ __align__(128) uint4 g_ahh[393216];   // w_hh fp16 hi
__device__ __align__(128) char g_bx[2][65536];   // B frags fp16 [x|h]
__device__ __align__(16) float g_cp[Tt * NGEMM * Bb]; // c partials [t][m][b]
__device__ __align__(16) float g_vp[2][8][Hh];
__device__ __align__(16) float g_v1[Hh];
__device__ __align__(16) float g_v2[Hh];
__device__ __align__(16) float g_bias[NN];
__device__ int g_mask_nzv[Bb];
__device__ unsigned g_hcnt, g_xcnt;
__device__ unsigned g_hrel, g_xrel;

// ===================== prep kernels =====================
__global__ void prep_pack_b(const float* __restrict__ features,
                            const float* __restrict__ b_ih,
                            const float* __restrict__ b_hh,
                            const float* __restrict__ mask) {
    int b = blockIdx.x, tid = threadIdx.x;
    int lane = tid & 31, wid = tid >> 5;
    if (b == 0 && tid == 0) { g_hcnt = 0u; g_xcnt = 0u; g_hrel = 0u; g_xrel = 0u; }
    int bi = b * 256 + tid;
    if (bi < N3) g_bias[bi] = b_ih[bi];
    else if (bi < NN) g_bias[bi] = b_hh[bi - N3];
    __shared__ unsigned wnz[8];
    float m0 = mask[b * Ss + tid], m1 = mask[b * Ss + tid + 256];
    unsigned bal = __ballot_sync(0xFFFFFFFFu, (m0 != 0.f) || (m1 != 0.f));
    if (lane == 0) wnz[wid] = bal;
    __syncthreads();
    if (tid == 0) {
        unsigned o = 0;
#pragma unroll
        for (int i = 0; i < 8; i++) o |= wnz[i];
        g_mask_nzv[b] = (o != 0u);
    }
#pragma unroll
    for (int jj = 0; jj < 4; jj++) {
        int j = tid + jj * 256;
        float v = features[b * Hh + j];
        uint32_t off = bx_off(j, b);
        *(unsigned short*)(g_bx[0] + off) = __half_as_ushort(__float2half_rn(v));
        *(unsigned short*)(g_bx[1] + off) = 0;
    }
}

__global__ void prep_v(const float* __restrict__ W1, const float* __restrict__ W2,
                       const float* __restrict__ V) {
    int hc = blockIdx.x, sel = blockIdx.y, tid = threadIdx.x;
    const float* W = sel ? W2 : W1;
    __shared__ float vs[128];
    if (tid < 128) vs[tid] = V[hc * 128 + tid];
    __syncthreads();
    float acc[4] = {0.f, 0.f, 0.f, 0.f};
    for (int h = 0; h < 128; h++) {
        const float* row = W + (size_t)(hc * 128 + h) * Hh;
        float vh = vs[h];
#pragma unroll
        for (int q = 0; q < 4; q++) acc[q] = fmaf(vh, row[tid + q * 256], acc[q]);
    }
#pragma unroll
    for (int q = 0; q < 4; q++) g_vp[sel][hc][tid + q * 256] = acc[q];
}

__global__ void prep_vred() {
    int i = blockIdx.x * 256 + threadIdx.x;
    int sel = i >> 10, d = i & 1023;
    float s = 0.f;
#pragma unroll
    for (int hc = 0; hc < 8; hc++) s += g_vp[sel][hc][d];
    if (sel) g_v2[d] = s; else g_v1[d] = s;
}

// pack W rows in triple-permuted A-fragment order: CTA m row rl -> W row (rl>>5)*1024 + m*32 + (rl&31)
__global__ void prep_wfr(const float* __restrict__ w_ih, const float* __restrict__ w_hh) {
    int idx = blockIdx.x * 256 + threadIdx.x;   // 393216
    int lane = idx & 31;
    int p = (idx >> 5) & 31;
    int rest = idx >> 10;                        // 0..383
    int wid = rest % 12;
    int m = rest / 12;
    int wm = wid >> 1, ks2 = wid & 1;
    int gq = lane >> 2, tq = lane & 3;
    int k0 = ks2 * 512 + p * 16 + 2 * tq;

    int rl[2] = {wm * 16 + gq, wm * 16 + gq + 8};
    float vx[8], vh4[8];
#pragma unroll
    for (int rr = 0; rr < 2; rr++) {
        int g = rl[rr] >> 5, jl = rl[rr] & 31;
        int Wrow = g * 1024 + m * 32 + jl;
        const float* Xr = w_ih + (size_t)Wrow * Hh;
        const float* Hr = w_hh + (size_t)Wrow * Hh;
        vx[rr * 2 + 0] = Xr[k0];     vx[rr * 2 + 1] = Xr[k0 + 1];
        vx[rr * 2 + 4] = Xr[k0 + 8]; vx[rr * 2 + 5] = Xr[k0 + 9];
        vh4[rr * 2 + 0] = Hr[k0];     vh4[rr * 2 + 1] = Hr[k0 + 1];
        vh4[rr * 2 + 4] = Hr[k0 + 8]; vh4[rr * 2 + 5] = Hr[k0 + 9];
    }
    uint32_t xh[4], xl[4], hh[4];
#pragma unroll
    for (int i = 0; i < 4; i++) {
        float a = vx[2 * i], b = vx[2 * i + 1];
        __half ha = __float2half_rn(a), hb = __float2half_rn(b);
        __half la = __float2half_rn((a - __half2float(ha)) * 4096.f);
        __half lb = __float2half_rn((b - __half2float(hb)) * 4096.f);
        xh[i] = pack_h2(ha, hb);
        xl[i] = pack_h2(la, lb);
        hh[i] = pack_h2(__float2half_rn(vh4[2 * i]), __float2half_rn(vh4[2 * i + 1]));
    }
    g_axh[idx] = make_uint4(xh[0], xh[1], xh[2], xh[3]);
    g_axl[idx] = make_uint4(xl[0], xl[1], xl[2], xl[3]);
    g_ahh[idx] = make_uint4(hh[0], hh[1], hh[2], hh[3]);
}

// ===================== persistent kernel =====================
extern __shared__ char dsm[];

__device__ __forceinline__ void stageB(const char* __restrict__ src, int tid) {
    uint32_t sb = smem_u32(dsm);
    for (int i = tid; i < 4096; i += THREADS) {
        asm volatile("cp.async.cg.shared.global [%0], [%1], 16;"
            :: "r"(sb + i * 16), "l"(__cvta_generic_to_global(src + i * 16)) : "memory");
    }
    asm volatile("cp.async.commit_group;" ::: "memory");
    asm volatile("cp.async.wait_group 0;" ::: "memory");
    __syncthreads();
}

__global__ void __launch_bounds__(THREADS, 1)
gru_persist(const float* __restrict__ inputs, const float* __restrict__ mask,
            float* __restrict__ probs, float* __restrict__ ctx) {
    const int c = blockIdx.x;            // 0..63
    const int tid = threadIdx.x;
    const int wid = tid >> 5;
    const int lane = tid & 31;

    // ================= scorer CTAs =================
    if (c >= NGEMM) {
        const int b2 = c - NGEMM;
        float* sa  = (float*)dsm;               // 512 f
        float* v2s = (float*)(dsm + 4096);      // 1024 f
        float* p   = (float*)(dsm + 8192);      // 512 f
        float* red2 = (float*)(dsm + 10240);
        int*   si2  = (int*)(dsm + 10496);
        int*   sfl  = (int*)(dsm + 10752);

        if (tid == 0) {
            int nz = 0;
#pragma unroll
            for (int i = 0; i < Bb; i++) nz |= g_mask_nzv[i];
            sfl[0] = nz;
        }
        for (int i = tid; i < Hh; i += THREADS) v2s[i] = g_v2[i];
        __syncthreads();
        const bool mask_nz = (sfl[0] != 0);

        // a[b2, s] = inputs[b2,s,:] . v2
        for (int row = wid; row < Ss; row += 12) {
            const float* r = inputs + ((size_t)b2 * Ss + row) * Hh;
            float acc = 0.f;
#pragma unroll
            for (int i = 0; i < 8; i++) {
                float4 x4 = *(const float4*)&r[(i * 32 + lane) * 4];
                float4 v4 = *(const float4*)&v2s[(i * 32 + lane) * 4];
                acc += x4.x * v4.x + x4.y * v4.y + x4.z * v4.z + x4.w * v4.w;
            }
#pragma unroll
            for (int o = 16; o > 0; o >>= 1) acc += __shfl_xor_sync(0xFFFFFFFFu, acc, o);
            if (lane == 0) sa[row] = acc;
        }
        __syncthreads();

        float mk0 = 0.f, mk1 = 0.f, a0 = 0.f, a1 = 0.f;
        if (tid < 256) {
            mk0 = mask[b2 * Ss + tid];
            mk1 = mask[b2 * Ss + tid + 256];
            a0 = sa[tid];
            a1 = sa[tid + 256];
        }

        for (int t = 0; t < Tt; t++) {
            if (tid == 0) { while (ld_acquire(&g_hrel) < (unsigned)(t + 1)) { } }
            __syncthreads();
            // c = sum_m g_cp[t][m][b2]
            if (tid < 32) {
                float v = g_cp[(t * NGEMM + tid) * Bb + b2];
#pragma unroll
                for (int o = 16; o > 0; o >>= 1) v += __shfl_xor_sync(0xFFFFFFFFu, v, o);
                if (tid == 0) red2[0] = v;
            }
            __syncthreads();
            const float c0v = red2[0];
            float s0 = 0.f, s1 = 0.f;
            if (tid < 256) {
                s0 = ftanh(c0v + a0);
                s1 = ftanh(c0v + a1);
                float* pr = probs + ((size_t)b2 * Tt + t) * Ss;
                pr[tid] = s0;
                pr[tid + 256] = s1;
            }
            if (t == 0 || mask_nz) {
                // argmax + gather + pack x
                if (tid < 256) {
                    float m0 = s0 + mk0, m1 = s1 + mk1;
                    float bv = m0; int bi = tid;
                    if (m1 > bv) { bv = m1; bi = tid + 256; }
#pragma unroll
                    for (int o = 16; o > 0; o >>= 1) {
                        float v = __shfl_xor_sync(0xFFFFFFFFu, bv, o);
                        int ii = __shfl_xor_sync(0xFFFFFFFFu, bi, o);
                        if (v > bv || (v == bv && ii < bi)) { bv = v; bi = ii; }
                    }
                    if (lane == 0) { red2[8 + wid] = bv; si2[wid] = bi; }
                }
                __syncthreads();
                if (tid == 0) {
                    float v = red2[8]; int ii = si2[0];
#pragma unroll
                    for (int i = 1; i < 8; i++) {
                        float v2 = red2[8 + i]; int i2 = si2[i];
                        if (v2 > v || (v2 == v && i2 < ii)) { v = v2; ii = i2; }
                    }
                    si2[15] = ii;
                }
                __syncthreads();
                int idx = si2[15];
                const float* xr = inputs + ((size_t)b2 * Ss + idx) * Hh;
                for (int k2 = tid; k2 < Hh; k2 += THREADS) {
                    *(unsigned short*)(g_bx[0] + bx_off(k2, b2)) =
                        __half_as_ushort(__float2half_rn(xr[k2]));
                }
                __syncthreads();
                if (tid == 0) {
                    unsigned prev = atom_add_acqrel(&g_xcnt, 1u);
                    if ((prev & 31u) == 31u) st_release(&g_xrel, (unsigned)(t + 1));
                }
            }
            if (t == 0) {
                // ctx for batch b2 (overlapped with remaining steps)
                for (int s = tid; s < Ss; s += THREADS)
                    p[s] = probs[(size_t)b2 * Tt * Ss + s] + mask[b2 * Ss + s];
                __syncthreads();
                if (tid < 256) {
                    float m = fmaxf(p[tid], p[tid + 256]);
#pragma unroll
                    for (int o = 16; o > 0; o >>= 1) m = fmaxf(m, __shfl_xor_sync(0xFFFFFFFFu, m, o));
                    if (lane == 0) red2[16 + wid] = m;
                }
                __syncthreads();
                if (tid == 0) {
                    float mm = red2[16];
#pragma unroll
                    for (int i = 1; i < 8; i++) mm = fmaxf(mm, red2[16 + i]);
                    red2[24] = mm;
                }
                __syncthreads();
                const float mx = red2[24];
                float sm = 0.f;
                if (tid < 256) {
                    float e0 = __expf(p[tid] - mx), e1 = __expf(p[tid + 256] - mx);
                    p[tid] = e0; p[tid + 256] = e1;
                    sm = e0 + e1;
#pragma unroll
                    for (int o = 16; o > 0; o >>= 1) sm += __shfl_xor_sync(0xFFFFFFFFu, sm, o);
                    if (lane == 0) red2[32 + wid] = sm;
                }
                __syncthreads();
                if (tid == 0) {
                    float ss = 0.f;
#pragma unroll
                    for (int i = 0; i < 8; i++) ss += red2[32 + i];
                    red2[40] = ss;
                }
                __syncthreads();
                const float Z = red2[40];
                if (tid < 256) {
                    float acc[4] = {0.f, 0.f, 0.f, 0.f};
                    for (int s = 0; s < Ss; s++) {
                        const float* row = inputs + ((size_t)b2 * Ss + s) * Hh;
                        float ps = p[s];
#pragma unroll
                        for (int q = 0; q < 4; q++) acc[q] = fmaf(ps, row[tid + q * 256], acc[q]);
                    }
#pragma unroll
                    for (int q = 0; q < 4; q++) ctx[b2 * Hh + tid + q * 256] = acc[q] / Z;
                }
                __syncthreads();
            }
        }
        return;
    }

    // ================= GEMM + fused-update CTAs =================
    const int m = c;                     // triple-tile / h-slice index
    const int wm = wid >> 1;             // M-chunk 0..5
    const int ks2 = wid & 1;             // K-half

    float* yb0  = (float*)(dsm + SM_Y0);
    float* yb1  = (float*)(dsm + SM_Y1);
    float* gxs  = (float*)(dsm + SM_GX);
    float* hold = (float*)(dsm + SM_HOLD);
    float* brS  = (float*)(dsm + SM_BIAS);
    float* bzS  = brS + 32;
    float* bniS = brS + 64;
    float* bnhS = brS + 96;
    float* v1S  = brS + 128;
    float* c32  = (float*)(dsm + SM_C32);
    int*   sfl  = (int*)(dsm + SM_FLG);

    if (tid == 0) {
        int nz = 0;
#pragma unroll
        for (int i = 0; i < Bb; i++) nz |= g_mask_nzv[i];
        sfl[0] = nz;
    }
    if (tid < 32) {
        int jg = m * 32 + tid;
        brS[tid] = g_bias[jg] + g_bias[3072 + jg];
        bzS[tid] = g_bias[1024 + jg] + g_bias[4096 + jg];
        bniS[tid] = g_bias[2048 + jg];
        bnhS[tid] = g_bias[5120 + jg];
        v1S[tid] = g_v1[jg];
    }
    for (int i = tid; i < 1024; i += THREADS) hold[i] = 0.f;
    __syncthreads();
    const bool mask_nz = (sfl[0] != 0);

    const size_t abase = ((size_t)(m * 12 + wid)) * 1024;
    const uint4* Axh = g_axh + abase;
    const uint4* Axl = g_axl + abase;
    const uint4* Ahh = g_ahh + abase;
    float* ybW = ks2 ? yb1 : yb0;
    const int r0 = wm * 16 + (lane >> 2);
    const int c0f = 2 * (lane & 3);

    for (int t = 0; t < Tt; t++) {
        const bool xp = (t <= 1) || mask_nz;
        const bool hp = (t >= 1);
        if (t >= 1) {
            if (tid == 0) {
                while (ld_acquire(&g_hrel) < (unsigned)t) { }
                if (xp) { while (ld_acquire(&g_xrel) < (unsigned)t) { } }
            }
            __syncthreads();
        }

        if (xp) {
            stageB(g_bx[0], tid);
            float acch[4][4], accl[4][4];
#pragma unroll
            for (int i = 0; i < 4; i++)
#pragma unroll
                for (int j = 0; j < 4; j++) { acch[i][j] = 0.f; accl[i][j] = 0.f; }
            uint4 AH[4], AL[4];
#pragma unroll
            for (int p = 0; p < 3; p++) { AH[p] = Axh[p * 32 + lane]; AL[p] = Axl[p * 32 + lane]; }
#pragma unroll
            for (int p = 0; p < 32; p++) {
                const int s = p & 3;
                if (p + 3 < 32) {
                    const int q = (p + 3) & 3;
                    AH[q] = Axh[(p + 3) * 32 + lane];
                    AL[q] = Axl[(p + 3) * 32 + lane];
                }
                const char* bb = dsm + (ks2 * 32 + p) * 1024 + lane * 8;
#pragma unroll
                for (int nn = 0; nn < 4; nn++) {
                    uint2 bv = *(const uint2*)(bb + nn * 256);
                    mma16816(acch[nn], &AH[s].x, bv.x, bv.y);
                    mma16816(accl[nn], &AL[s].x, bv.x, bv.y);
                }
            }
#pragma unroll
            for (int nn = 0; nn < 4; nn++) {
                int col = nn * 8 + c0f;
                ybW[r0 * 32 + col]           = acch[nn][0] + accl[nn][0] * (1.f / 4096.f);
                ybW[r0 * 32 + col + 1]       = acch[nn][1] + accl[nn][1] * (1.f / 4096.f);
                ybW[(r0 + 8) * 32 + col]     = acch[nn][2] + accl[nn][2] * (1.f / 4096.f);
                ybW[(r0 + 8) * 32 + col + 1] = acch[nn][3] + accl[nn][3] * (1.f / 4096.f);
            }
            __syncthreads();
            for (int i = tid; i < 3072; i += THREADS) gxs[i] = yb0[i] + yb1[i];
            __syncthreads();
        }

        if (hp) {
            stageB(g_bx[1], tid);
            float acch[4][4];
#pragma unroll
            for (int i = 0; i < 4; i++)
#pragma unroll
                for (int j = 0; j < 4; j++) acch[i][j] = 0.f;
            uint4 AH[4];
#pragma unroll
            for (int p = 0; p < 3; p++) AH[p] = Ahh[p * 32 + lane];
#pragma unroll
            for (int p = 0; p < 32; p++) {
                const int s = p & 3;
                if (p + 3 < 32) AH[(p + 3) & 3] = Ahh[(p + 3) * 32 + lane];
                const char* bb = dsm + (ks2 * 32 + p) * 1024 + lane * 8;
#pragma unroll
                for (int nn = 0; nn < 4; nn++) {
                    uint2 bv = *(const uint2*)(bb + nn * 256);
                    mma16816(acch[nn], &AH[s].x, bv.x, bv.y);
                }
            }
#pragma unroll
            for (int nn = 0; nn < 4; nn++) {
                int col = nn * 8 + c0f;
                ybW[r0 * 32 + col]           = acch[nn][0];
                ybW[r0 * 32 + col + 1]       = acch[nn][1];
                ybW[(r0 + 8) * 32 + col]     = acch[nn][2];
                ybW[(r0 + 8) * 32 + col + 1] = acch[nn][3];
            }
            __syncthreads();
        }

        if (tid < 32) c32[tid] = 0.f;
        __syncthreads();

        // ---- fused GRU update for h[m*32 .. m*32+32) x 32 batches ----
        for (int i = tid; i < 1024; i += THREADS) {
            int jl = i >> 5, b = i & 31;
            float yr = 0.f, yz = 0.f, yn = 0.f;
            if (hp) {
                yr = yb0[jl * 32 + b] + yb1[jl * 32 + b];
                yz = yb0[(32 + jl) * 32 + b] + yb1[(32 + jl) * 32 + b];
                yn = yb0[(64 + jl) * 32 + b] + yb1[(64 + jl) * 32 + b];
            }
            float gir = gxs[jl * 32 + b];
            float giz = gxs[(32 + jl) * 32 + b];
            float gin = gxs[(64 + jl) * 32 + b];
            float r = fsigmoid(gir + yr + brS[jl]);
            float z = fsigmoid(giz + yz + bzS[jl]);
            float nv = ftanh(gin + bniS[jl] + r * (yn + bnhS[jl]));
            float hnew = (1.f - z) * nv + z * hold[i];
            hold[i] = hnew;
            *(unsigned short*)(g_bx[1] + bx_off(m * 32 + jl, b)) =
                __half_as_ushort(__float2half_rn(hnew));
            atomicAdd(&c32[b], v1S[jl] * hnew);
        }
        __syncthreads();
        if (tid < 32) g_cp[(t * NGEMM + m) * Bb + tid] = c32[tid];
        __syncthreads();
        if (tid == 0) {
            unsigned prev = atom_add_acqrel(&g_hcnt, 1u);
            if ((prev & 31u) == 31u) st_release(&g_hrel, (unsigned)(t + 1));
        }
    }
}

// ===================== launch =====================
extern "C" void kernel_launch(void* const* d_in, const int* in_sizes, int n_in,
                              void* d_out, int out_size) {
    const float* inputs   = (const float*)d_in[0];
    const float* mask     = (const float*)d_in[1];
    // d_in[2] = inputs_embeds (unused, use_emb=False)
    const float* features = (const float*)d_in[3];
    const float* w_ih     = (const float*)d_in[4];
    const float* b_ih     = (const float*)d_in[5];
    const float* w_hh     = (const float*)d_in[6];
    const float* b_hh     = (const float*)d_in[7];
    const float* W1       = (const float*)d_in[8];
    const float* W2       = (const float*)d_in[9];
    const float* V        = (const float*)d_in[10];

    float* out   = (float*)d_out;
    float* probs = out;                            // [B, T, S]
    float* ctx   = out + (size_t)Bb * Tt * Ss;     // [B, H]

    cudaFuncSetAttribute(gru_persist, cudaFuncAttributeMaxDynamicSharedMemorySize, DSMEM);

    prep_pack_b<<<Bb, 256>>>(features, b_ih, b_hh, mask);
    prep_v<<<dim3(8, 2), 256>>>(W1, W2, V);
    prep_vred<<<8, 256>>>();
    prep_wfr<<<1536, 256>>>(w_ih, w_hh);

    gru_persist<<<GRID, THREADS, DSMEM>>>(inputs, mask, probs, ctx);
}

// round 13
// speedup vs baseline: 2.4949x; 1.3201x over previous
#include <cuda_runtime.h>
#include <cuda_fp16.h>
#include <cstdint>
#include <math.h>

#define Bb 32
#define Hh 1024
#define Ss 512
#define Tt 32
#define N3 3072
#define NN 6144
#define NGEMM 64
#define GRID 96
#define THREADS 384

// smem layout (GEMM CTAs)
#define SM_B 0            // 65536: B stage (fp16 frags, full K)
#define SM_Y 65536        // 24576: y [kq 4][48][32] f32
#define SM_GX 90112       // 6144: cached gi [48][32]
#define SM_HOLD 96256     // 2048: hold h [16][32]
#define SM_BIAS 98304     // 384: br,bz,bni,bnh,v1 x16
#define SM_C32W 98688     // 1536: [12][32] c partial per warp
#define SM_RED 100224     // 128
#define SM_FLG 100352     // 16
#define DSMEM 100480

// ===================== helpers =====================
__device__ __forceinline__ uint32_t smem_u32(const void* p) {
    uint32_t a;
    asm("{ .reg .u64 t; cvta.to.shared.u64 t, %1; cvt.u32.u64 %0, t; }" : "=r"(a) : "l"(p));
    return a;
}
__device__ __forceinline__ uint32_t pack_h2(__half x, __half y) {
    return (uint32_t)__half_as_ushort(x) | ((uint32_t)__half_as_ushort(y) << 16);
}
__device__ __forceinline__ float fsigmoid(float x) { return 1.f / (1.f + __expf(-x)); }
__device__ __forceinline__ float ftanh(float x) { return 2.f / (1.f + __expf(-2.f * x)) - 1.f; }
__device__ __forceinline__ void mma16816(float* c, const uint32_t* a, uint32_t b0, uint32_t b1) {
    asm volatile(
        "mma.sync.aligned.m16n8k16.row.col.f32.f16.f16.f32 "
        "{%0,%1,%2,%3}, {%4,%5,%6,%7}, {%8,%9}, {%0,%1,%2,%3};"
        : "+f"(c[0]), "+f"(c[1]), "+f"(c[2]), "+f"(c[3])
        : "r"(a[0]), "r"(a[1]), "r"(a[2]), "r"(a[3]), "r"(b0), "r"(b1));
}
// B-fragment byte offset for (k=j in [0,1024), n=b)
__device__ __forceinline__ uint32_t bx_off(int j, int b) {
    int kc = j >> 4, r = j & 15;
    int nn = b >> 3, g = b & 7, t = (r & 7) >> 1;
    return (uint32_t)(kc * 1024 + nn * 256 + (g * 4 + t) * 8 + ((r >= 8) ? 4 : 0) + (r & 1) * 2);
}
__device__ __forceinline__ unsigned atom_add_acqrel(unsigned* p, unsigned v) {
    unsigned old;
    asm volatile("atom.add.acq_rel.gpu.u32 %0, [%1], %2;" : "=r"(old) : "l"(p), "r"(v) : "memory");
    return old;
}
__device__ __forceinline__ unsigned ld_acquire(unsigned* p) {
    unsigned v;
    asm volatile("ld.acquire.gpu.u32 %0, [%1];" : "=r"(v) : "l"(p) : "memory");
    return v;
}
__device__ __forceinline__ void st_release(unsigned* p, unsigned v) {
    asm volatile("st.release.gpu.u32 [%0], %1;" :: "l"(p), "r"(v) : "memory");
}

// ===================== device scratch =====================
// A fragments: [m 64][wid 12][p 16][lane 32] uint4
// CTA m, warp wid = wm*4+kq: gate wm, h-slice m*16.., K-quarter kq
__device__ __align__(128) uint4 g_axh[393216];   // w_ih fp16 hi
__device__ __align__(128) uint4 g_axl[393216];   // w_ih fp16 lo (x4096)
__device__ __align__(128) uint4 g_ahh[393216];   // w_hh fp16 hi
__device__ __align__(128) char g_bx[2][65536];   // B frags fp16 [x|h]
__device__ __align__(16) float g_cp[Tt * NGEMM * Bb]; // c partials [t][m][b]
__device__ __align__(16) float g_vp[2][8][Hh];
__device__ __align__(16) float g_v1[Hh];
__device__ __align__(16) float g_v2[Hh];
__device__ __align__(16) float g_bias[NN];
__device__ int g_mask_nzv[Bb];
__device__ unsigned g_hcnt, g_xcnt;
__device__ unsigned g_hrel, g_xrel;

// ===================== prep kernels =====================
__global__ void prep_pack_b(const float* __restrict__ features,
                            const float* __restrict__ b_ih,
                            const float* __restrict__ b_hh,
                            const float* __restrict__ mask) {
    int b = blockIdx.x, tid = threadIdx.x;
    int lane = tid & 31, wid = tid >> 5;
    if (b == 0 && tid == 0) { g_hcnt = 0u; g_xcnt = 0u; g_hrel = 0u; g_xrel = 0u; }
    int bi = b * 256 + tid;
    if (bi < N3) g_bias[bi] = b_ih[bi];
    else if (bi < NN) g_bias[bi] = b_hh[bi - N3];
    __shared__ unsigned wnz[8];
    float m0 = mask[b * Ss + tid], m1 = mask[b * Ss + tid + 256];
    unsigned bal = __ballot_sync(0xFFFFFFFFu, (m0 != 0.f) || (m1 != 0.f));
    if (lane == 0) wnz[wid] = bal;
    __syncthreads();
    if (tid == 0) {
        unsigned o = 0;
#pragma unroll
        for (int i = 0; i < 8; i++) o |= wnz[i];
        g_mask_nzv[b] = (o != 0u);
    }
#pragma unroll
    for (int jj = 0; jj < 4; jj++) {
        int j = tid + jj * 256;
        float v = features[b * Hh + j];
        uint32_t off = bx_off(j, b);
        *(unsigned short*)(g_bx[0] + off) = __half_as_ushort(__float2half_rn(v));
        *(unsigned short*)(g_bx[1] + off) = 0;
    }
}

__global__ void prep_v(const float* __restrict__ W1, const float* __restrict__ W2,
                       const float* __restrict__ V) {
    int hc = blockIdx.x, sel = blockIdx.y, tid = threadIdx.x;
    const float* W = sel ? W2 : W1;
    __shared__ float vs[128];
    if (tid < 128) vs[tid] = V[hc * 128 + tid];
    __syncthreads();
    float acc[4] = {0.f, 0.f, 0.f, 0.f};
    for (int h = 0; h < 128; h++) {
        const float* row = W + (size_t)(hc * 128 + h) * Hh;
        float vh = vs[h];
#pragma unroll
        for (int q = 0; q < 4; q++) acc[q] = fmaf(vh, row[tid + q * 256], acc[q]);
    }
#pragma unroll
    for (int q = 0; q < 4; q++) g_vp[sel][hc][tid + q * 256] = acc[q];
}

__global__ void prep_vred() {
    int i = blockIdx.x * 256 + threadIdx.x;
    int sel = i >> 10, d = i & 1023;
    float s = 0.f;
#pragma unroll
    for (int hc = 0; hc < 8; hc++) s += g_vp[sel][hc][d];
    if (sel) g_v2[d] = s; else g_v1[d] = s;
}

// pack W rows: CTA m, warp (wm,kq) -> gate wm, rows m*16+jl, K-quarter kq
__global__ void prep_wfr(const float* __restrict__ w_ih, const float* __restrict__ w_hh) {
    int idx = blockIdx.x * 256 + threadIdx.x;   // 393216
    int lane = idx & 31;
    int p = (idx >> 5) & 15;
    int rest = idx >> 9;                         // 0..767
    int wid = rest % 12;
    int m = rest / 12;
    int wm = wid >> 2, kq = wid & 3;
    int gq = lane >> 2, tq = lane & 3;
    int k0 = kq * 256 + p * 16 + 2 * tq;

    int jl[2] = {gq, gq + 8};
    float vx[8], vh4[8];
#pragma unroll
    for (int rr = 0; rr < 2; rr++) {
        int Wrow = wm * 1024 + m * 16 + jl[rr];
        const float* Xr = w_ih + (size_t)Wrow * Hh;
        const float* Hr = w_hh + (size_t)Wrow * Hh;
        vx[rr * 2 + 0] = Xr[k0];     vx[rr * 2 + 1] = Xr[k0 + 1];
        vx[rr * 2 + 4] = Xr[k0 + 8]; vx[rr * 2 + 5] = Xr[k0 + 9];
        vh4[rr * 2 + 0] = Hr[k0];     vh4[rr * 2 + 1] = Hr[k0 + 1];
        vh4[rr * 2 + 4] = Hr[k0 + 8]; vh4[rr * 2 + 5] = Hr[k0 + 9];
    }
    uint32_t xh[4], xl[4], hh[4];
#pragma unroll
    for (int i = 0; i < 4; i++) {
        float a = vx[2 * i], b = vx[2 * i + 1];
        __half ha = __float2half_rn(a), hb = __float2half_rn(b);
        __half la = __float2half_rn((a - __half2float(ha)) * 4096.f);
        __half lb = __float2half_rn((b - __half2float(hb)) * 4096.f);
        xh[i] = pack_h2(ha, hb);
        xl[i] = pack_h2(la, lb);
        hh[i] = pack_h2(__float2half_rn(vh4[2 * i]), __float2half_rn(vh4[2 * i + 1]));
    }
    g_axh[idx] = make_uint4(xh[0], xh[1], xh[2], xh[3]);
    g_axl[idx] = make_uint4(xl[0], xl[1], xl[2], xl[3]);
    g_ahh[idx] = make_uint4(hh[0], hh[1], hh[2], hh[3]);
}

// ===================== persistent kernel =====================
extern __shared__ char dsm[];

__device__ __forceinline__ void stageB(const char* __restrict__ src, int tid) {
    uint32_t sb = smem_u32(dsm);
    for (int i = tid; i < 4096; i += THREADS) {
        asm volatile("cp.async.cg.shared.global [%0], [%1], 16;"
            :: "r"(sb + i * 16), "l"(__cvta_generic_to_global(src + i * 16)) : "memory");
    }
    asm volatile("cp.async.commit_group;" ::: "memory");
    asm volatile("cp.async.wait_group 0;" ::: "memory");
    __syncthreads();
}

__global__ void __launch_bounds__(THREADS, 1)
gru_persist(const float* __restrict__ inputs, const float* __restrict__ mask,
            float* __restrict__ probs, float* __restrict__ ctx) {
    const int c = blockIdx.x;            // 0..95
    const int tid = threadIdx.x;
    const int wid = tid >> 5;
    const int lane = tid & 31;

    // ================= scorer CTAs =================
    if (c >= NGEMM) {
        const int b2 = c - NGEMM;
        float* sa  = (float*)dsm;               // 512 f
        float* v2s = (float*)(dsm + 4096);      // 1024 f
        float* p   = (float*)(dsm + 8192);      // 512 f
        float* red2 = (float*)(dsm + 10240);
        int*   si2  = (int*)(dsm + 10496);
        int*   sfl  = (int*)(dsm + 10752);

        if (tid == 0) {
            int nz = 0;
#pragma unroll
            for (int i = 0; i < Bb; i++) nz |= g_mask_nzv[i];
            sfl[0] = nz;
        }
        for (int i = tid; i < Hh; i += THREADS) v2s[i] = g_v2[i];
        __syncthreads();
        const bool mask_nz = (sfl[0] != 0);

        // a[b2, s] = inputs[b2,s,:] . v2
        for (int row = wid; row < Ss; row += 12) {
            const float* r = inputs + ((size_t)b2 * Ss + row) * Hh;
            float acc = 0.f;
#pragma unroll
            for (int i = 0; i < 8; i++) {
                float4 x4 = *(const float4*)&r[(i * 32 + lane) * 4];
                float4 v4 = *(const float4*)&v2s[(i * 32 + lane) * 4];
                acc += x4.x * v4.x + x4.y * v4.y + x4.z * v4.z + x4.w * v4.w;
            }
#pragma unroll
            for (int o = 16; o > 0; o >>= 1) acc += __shfl_xor_sync(0xFFFFFFFFu, acc, o);
            if (lane == 0) sa[row] = acc;
        }
        __syncthreads();

        float mk0 = 0.f, mk1 = 0.f, a0 = 0.f, a1 = 0.f;
        if (tid < 256) {
            mk0 = mask[b2 * Ss + tid];
            mk1 = mask[b2 * Ss + tid + 256];
            a0 = sa[tid];
            a1 = sa[tid + 256];
        }

        for (int t = 0; t < Tt; t++) {
            if (tid == 0) { while (ld_acquire(&g_hrel) < (unsigned)(t + 1)) { } }
            __syncthreads();
            // c = sum over 64 partials
            if (tid < 64) {
                float v = g_cp[(t * NGEMM + tid) * Bb + b2];
#pragma unroll
                for (int o = 16; o > 0; o >>= 1) v += __shfl_xor_sync(0xFFFFFFFFu, v, o);
                if (lane == 0) red2[wid] = v;
            }
            __syncthreads();
            const float c0v = red2[0] + red2[1];
            float s0 = 0.f, s1 = 0.f;
            if (tid < 256) {
                s0 = ftanh(c0v + a0);
                s1 = ftanh(c0v + a1);
                float* pr = probs + ((size_t)b2 * Tt + t) * Ss;
                pr[tid] = s0;
                pr[tid + 256] = s1;
            }
            if (t == 0 || mask_nz) {
                if (tid < 256) {
                    float m0 = s0 + mk0, m1 = s1 + mk1;
                    float bv = m0; int bi = tid;
                    if (m1 > bv) { bv = m1; bi = tid + 256; }
#pragma unroll
                    for (int o = 16; o > 0; o >>= 1) {
                        float v = __shfl_xor_sync(0xFFFFFFFFu, bv, o);
                        int ii = __shfl_xor_sync(0xFFFFFFFFu, bi, o);
                        if (v > bv || (v == bv && ii < bi)) { bv = v; bi = ii; }
                    }
                    if (lane == 0) { red2[8 + wid] = bv; si2[wid] = bi; }
                }
                __syncthreads();
                if (tid == 0) {
                    float v = red2[8]; int ii = si2[0];
#pragma unroll
                    for (int i = 1; i < 8; i++) {
                        float v2 = red2[8 + i]; int i2 = si2[i];
                        if (v2 > v || (v2 == v && i2 < ii)) { v = v2; ii = i2; }
                    }
                    si2[15] = ii;
                }
                __syncthreads();
                int idx = si2[15];
                const float* xr = inputs + ((size_t)b2 * Ss + idx) * Hh;
                for (int k2 = tid; k2 < Hh; k2 += THREADS) {
                    *(unsigned short*)(g_bx[0] + bx_off(k2, b2)) =
                        __half_as_ushort(__float2half_rn(xr[k2]));
                }
                __syncthreads();
                if (tid == 0) {
                    unsigned prev = atom_add_acqrel(&g_xcnt, 1u);
                    if ((prev & 31u) == 31u) st_release(&g_xrel, (unsigned)(t + 1));
                }
            }
            if (t == 0) {
                // ctx for batch b2 (overlapped with remaining steps)
                for (int s = tid; s < Ss; s += THREADS)
                    p[s] = probs[(size_t)b2 * Tt * Ss + s] + mask[b2 * Ss + s];
                __syncthreads();
                if (tid < 256) {
                    float m = fmaxf(p[tid], p[tid + 256]);
#pragma unroll
                    for (int o = 16; o > 0; o >>= 1) m = fmaxf(m, __shfl_xor_sync(0xFFFFFFFFu, m, o));
                    if (lane == 0) red2[16 + wid] = m;
                }
                __syncthreads();
                if (tid == 0) {
                    float mm = red2[16];
#pragma unroll
                    for (int i = 1; i < 8; i++) mm = fmaxf(mm, red2[16 + i]);
                    red2[24] = mm;
                }
                __syncthreads();
                const float mx = red2[24];
                float sm = 0.f;
                if (tid < 256) {
                    float e0 = __expf(p[tid] - mx), e1 = __expf(p[tid + 256] - mx);
                    p[tid] = e0; p[tid + 256] = e1;
                    sm = e0 + e1;
#pragma unroll
                    for (int o = 16; o > 0; o >>= 1) sm += __shfl_xor_sync(0xFFFFFFFFu, sm, o);
                    if (lane == 0) red2[32 + wid] = sm;
                }
                __syncthreads();
                if (tid == 0) {
                    float ss = 0.f;
#pragma unroll
                    for (int i = 0; i < 8; i++) ss += red2[32 + i];
                    red2[40] = ss;
                }
                __syncthreads();
                const float Z = red2[40];
                if (tid < 256) {
                    float acc[4] = {0.f, 0.f, 0.f, 0.f};
                    for (int s = 0; s < Ss; s++) {
                        const float* row = inputs + ((size_t)b2 * Ss + s) * Hh;
                        float ps = p[s];
#pragma unroll
                        for (int q = 0; q < 4; q++) acc[q] = fmaf(ps, row[tid + q * 256], acc[q]);
                    }
#pragma unroll
                    for (int q = 0; q < 4; q++) ctx[b2 * Hh + tid + q * 256] = acc[q] / Z;
                }
                __syncthreads();
            }
        }
        return;
    }

    // ================= GEMM + fused-update CTAs =================
    const int m = c;                     // h-slice index (16 h values)
    const int wm = wid >> 2;             // gate 0..2
    const int kq = wid & 3;              // K-quarter

    float* yq   = (float*)(dsm + SM_Y);          // [kq][48][32]
    float* gxs  = (float*)(dsm + SM_GX);         // [48][32]
    float* hold = (float*)(dsm + SM_HOLD);       // [16][32]
    float* brS  = (float*)(dsm + SM_BIAS);
    float* bzS  = brS + 16;
    float* bniS = brS + 32;
    float* bnhS = brS + 48;
    float* v1S  = brS + 64;
    float* c32w = (float*)(dsm + SM_C32W);       // [12][32]
    int*   sfl  = (int*)(dsm + SM_FLG);

    if (tid == 0) {
        int nz = 0;
#pragma unroll
        for (int i = 0; i < Bb; i++) nz |= g_mask_nzv[i];
        sfl[0] = nz;
    }
    if (tid < 16) {
        int jg = m * 16 + tid;
        brS[tid] = g_bias[jg] + g_bias[3072 + jg];
        bzS[tid] = g_bias[1024 + jg] + g_bias[4096 + jg];
        bniS[tid] = g_bias[2048 + jg];
        bnhS[tid] = g_bias[5120 + jg];
        v1S[tid] = g_v1[jg];
    }
    for (int i = tid; i < 512; i += THREADS) hold[i] = 0.f;
    __syncthreads();
    const bool mask_nz = (sfl[0] != 0);

    const size_t abase = ((size_t)(m * 12 + wid)) * 512;   // [m][wid][p][lane]
    const uint4* Axh = g_axh + abase;
    const uint4* Axl = g_axl + abase;
    const uint4* Ahh = g_ahh + abase;
    float* ybW = yq + kq * 1536;         // this warp's K-quarter buffer
    const int r0 = wm * 16 + (lane >> 2);
    const int c0f = 2 * (lane & 3);

    for (int t = 0; t < Tt; t++) {
        const bool xp = (t <= 1) || mask_nz;
        const bool hp = (t >= 1);
        if (t >= 1) {
            if (tid == 0) {
                while (ld_acquire(&g_hrel) < (unsigned)t) { }
                if (xp) { while (ld_acquire(&g_xrel) < (unsigned)t) { } }
            }
            __syncthreads();
        }

        if (xp) {
            stageB(g_bx[0], tid);
            float acch[4][4], accl[4][4];
#pragma unroll
            for (int i = 0; i < 4; i++)
#pragma unroll
                for (int j = 0; j < 4; j++) { acch[i][j] = 0.f; accl[i][j] = 0.f; }
            uint4 AH[4], AL[4];
#pragma unroll
            for (int p = 0; p < 3; p++) { AH[p] = Axh[p * 32 + lane]; AL[p] = Axl[p * 32 + lane]; }
#pragma unroll
            for (int p = 0; p < 16; p++) {
                const int s = p & 3;
                if (p + 3 < 16) {
                    const int q = (p + 3) & 3;
                    AH[q] = Axh[(p + 3) * 32 + lane];
                    AL[q] = Axl[(p + 3) * 32 + lane];
                }
                const char* bb = dsm + (kq * 16 + p) * 1024 + lane * 8;
#pragma unroll
                for (int nn = 0; nn < 4; nn++) {
                    uint2 bv = *(const uint2*)(bb + nn * 256);
                    mma16816(acch[nn], &AH[s].x, bv.x, bv.y);
                    mma16816(accl[nn], &AL[s].x, bv.x, bv.y);
                }
            }
#pragma unroll
            for (int nn = 0; nn < 4; nn++) {
                int col = nn * 8 + c0f;
                ybW[r0 * 32 + col]           = acch[nn][0] + accl[nn][0] * (1.f / 4096.f);
                ybW[r0 * 32 + col + 1]       = acch[nn][1] + accl[nn][1] * (1.f / 4096.f);
                ybW[(r0 + 8) * 32 + col]     = acch[nn][2] + accl[nn][2] * (1.f / 4096.f);
                ybW[(r0 + 8) * 32 + col + 1] = acch[nn][3] + accl[nn][3] * (1.f / 4096.f);
            }
            __syncthreads();
            for (int i = tid; i < 1536; i += THREADS)
                gxs[i] = yq[i] + yq[1536 + i] + yq[3072 + i] + yq[4608 + i];
            __syncthreads();
        }

        if (hp) {
            stageB(g_bx[1], tid);
            float acch[4][4];
#pragma unroll
            for (int i = 0; i < 4; i++)
#pragma unroll
                for (int j = 0; j < 4; j++) acch[i][j] = 0.f;
            uint4 AH[4];
#pragma unroll
            for (int p = 0; p < 3; p++) AH[p] = Ahh[p * 32 + lane];
#pragma unroll
            for (int p = 0; p < 16; p++) {
                const int s = p & 3;
                if (p + 3 < 16) AH[(p + 3) & 3] = Ahh[(p + 3) * 32 + lane];
                const char* bb = dsm + (kq * 16 + p) * 1024 + lane * 8;
#pragma unroll
                for (int nn = 0; nn < 4; nn++) {
                    uint2 bv = *(const uint2*)(bb + nn * 256);
                    mma16816(acch[nn], &AH[s].x, bv.x, bv.y);
                }
            }
#pragma unroll
            for (int nn = 0; nn < 4; nn++) {
                int col = nn * 8 + c0f;
                ybW[r0 * 32 + col]           = acch[nn][0];
                ybW[r0 * 32 + col + 1]       = acch[nn][1];
                ybW[(r0 + 8) * 32 + col]     = acch[nn][2];
                ybW[(r0 + 8) * 32 + col + 1] = acch[nn][3];
            }
            __syncthreads();
        }

        // ---- fused GRU update for h[m*16 .. m*16+16) x 32 batches ----
        float cacc = 0.f;
        for (int i = tid; i < 512; i += THREADS) {
            int jl = i >> 5, b = i & 31;
            float yr = 0.f, yz = 0.f, yn = 0.f;
            if (hp) {
                yr = yq[jl * 32 + b]        + yq[1536 + jl * 32 + b]
                   + yq[3072 + jl * 32 + b] + yq[4608 + jl * 32 + b];
                yz = yq[(16 + jl) * 32 + b]        + yq[1536 + (16 + jl) * 32 + b]
                   + yq[3072 + (16 + jl) * 32 + b] + yq[4608 + (16 + jl) * 32 + b];
                yn = yq[(32 + jl) * 32 + b]        + yq[1536 + (32 + jl) * 32 + b]
                   + yq[3072 + (32 + jl) * 32 + b] + yq[4608 + (32 + jl) * 32 + b];
            }
            float gir = gxs[jl * 32 + b];
            float giz = gxs[(16 + jl) * 32 + b];
            float gin = gxs[(32 + jl) * 32 + b];
            float r = fsigmoid(gir + yr + brS[jl]);
            float z = fsigmoid(giz + yz + bzS[jl]);
            float nv = ftanh(gin + bniS[jl] + r * (yn + bnhS[jl]));
            float hnew = (1.f - z) * nv + z * hold[i];
            hold[i] = hnew;
            *(unsigned short*)(g_bx[1] + bx_off(m * 16 + jl, b)) =
                __half_as_ushort(__float2half_rn(hnew));
            cacc = fmaf(v1S[jl], hnew, cacc);
        }
        // conflict-free c reduction: per-warp lane==b partials, then 32-thread sum
        c32w[wid * 32 + lane] = cacc;
        __syncthreads();
        if (tid < 32) {
            float s = 0.f;
#pragma unroll
            for (int w = 0; w < 12; w++) s += c32w[w * 32 + tid];
            g_cp[(t * NGEMM + m) * Bb + tid] = s;
        }
        __syncthreads();
        if (tid == 0) {
            unsigned prev = atom_add_acqrel(&g_hcnt, 1u);
            if ((prev & 63u) == 63u) st_release(&g_hrel, (unsigned)(t + 1));
        }
    }
}

// ===================== launch =====================
extern "C" void kernel_launch(void* const* d_in, const int* in_sizes, int n_in,
                              void* d_out, int out_size) {
    const float* inputs   = (const float*)d_in[0];
    const float* mask     = (const float*)d_in[1];
    // d_in[2] = inputs_embeds (unused, use_emb=False)
    const float* features = (const float*)d_in[3];
    const float* w_ih     = (const float*)d_in[4];
    const float* b_ih     = (const float*)d_in[5];
    const float* w_hh     = (const float*)d_in[6];
    const float* b_hh     = (const float*)d_in[7];
    const float* W1       = (const float*)d_in[8];
    const float* W2       = (const float*)d_in[9];
    const float* V        = (const float*)d_in[10];

    float* out   = (float*)d_out;
    float* probs = out;                            // [B, T, S]
    float* ctx   = out + (size_t)Bb * Tt * Ss;     // [B, H]

    cudaFuncSetAttribute(gru_persist, cudaFuncAttributeMaxDynamicSharedMemorySize, DSMEM);

    prep_pack_b<<<Bb, 256>>>(features, b_ih, b_hh, mask);
    prep_v<<<dim3(8, 2), 256>>>(W1, W2, V);
    prep_vred<<<8, 256>>>();
    prep_wfr<<<1536, 256>>>(w_ih, w_hh);

    gru_persist<<<GRID, THREADS, DSMEM>>>(inputs, mask, probs, ctx);
}

// round 14
// speedup vs baseline: 2.5609x; 1.0265x over previous
#include <cuda_runtime.h>
#include <cuda_fp16.h>
#include <cstdint>
#include <math.h>

#define Bb 32
#define Hh 1024
#define Ss 512
#define Tt 32
#define N3 3072
#define NN 6144
#define NGEMM 128        // 64 h-slices x 2 batch-halves
#define NSCOR 16         // 2 batches each
#define GRID 144
#define THREADS 384

// smem layout (GEMM CTAs)
#define SM_B 0            // 32768: B stage (own batch-half, compacted)
#define SM_Y 32768        // 12288: y [kq 4][48][16] f32
#define SM_GX 45056       // 3072: cached gi [48][16]
#define SM_HOLD 48128     // 1024: hold h [16][16]
#define SM_BIAS 49152     // 320: br,bz,bni,bnh,v1 x16
#define SM_C256 49472     // 1024: [256] c elements
#define SM_FLG 50496      // 16
#define DSMEM 50688

// ===================== helpers =====================
__device__ __forceinline__ uint32_t smem_u32(const void* p) {
    uint32_t a;
    asm("{ .reg .u64 t; cvta.to.shared.u64 t, %1; cvt.u32.u64 %0, t; }" : "=r"(a) : "l"(p));
    return a;
}
__device__ __forceinline__ uint32_t pack_h2(__half x, __half y) {
    return (uint32_t)__half_as_ushort(x) | ((uint32_t)__half_as_ushort(y) << 16);
}
__device__ __forceinline__ float fsigmoid(float x) { return 1.f / (1.f + __expf(-x)); }
__device__ __forceinline__ float ftanh(float x) { return 2.f / (1.f + __expf(-2.f * x)) - 1.f; }
__device__ __forceinline__ void mma16816(float* c, const uint32_t* a, uint32_t b0, uint32_t b1) {
    asm volatile(
        "mma.sync.aligned.m16n8k16.row.col.f32.f16.f16.f32 "
        "{%0,%1,%2,%3}, {%4,%5,%6,%7}, {%8,%9}, {%0,%1,%2,%3};"
        : "+f"(c[0]), "+f"(c[1]), "+f"(c[2]), "+f"(c[3])
        : "r"(a[0]), "r"(a[1]), "r"(a[2]), "r"(a[3]), "r"(b0), "r"(b1));
}
// B-fragment byte offset for (k=j in [0,1024), n=b in [0,32))
__device__ __forceinline__ uint32_t bx_off(int j, int b) {
    int kc = j >> 4, r = j & 15;
    int nn = b >> 3, g = b & 7, t = (r & 7) >> 1;
    return (uint32_t)(kc * 1024 + nn * 256 + (g * 4 + t) * 8 + ((r >= 8) ? 4 : 0) + (r & 1) * 2);
}
__device__ __forceinline__ unsigned atom_add_acqrel(unsigned* p, unsigned v) {
    unsigned old;
    asm volatile("atom.add.acq_rel.gpu.u32 %0, [%1], %2;" : "=r"(old) : "l"(p), "r"(v) : "memory");
    return old;
}
__device__ __forceinline__ unsigned ld_acquire(unsigned* p) {
    unsigned v;
    asm volatile("ld.acquire.gpu.u32 %0, [%1];" : "=r"(v) : "l"(p) : "memory");
    return v;
}
__device__ __forceinline__ void st_release(unsigned* p, unsigned v) {
    asm volatile("st.release.gpu.u32 [%0], %1;" :: "l"(p), "r"(v) : "memory");
}

// ===================== device scratch =====================
// A fragments: [m 64][wid 12][p 16][lane 32] uint4 (warp wid = gate*4 + kq)
__device__ __align__(128) uint4 g_axh[393216];   // w_ih fp16 hi
__device__ __align__(128) uint4 g_axl[393216];   // w_ih fp16 lo (x4096)
__device__ __align__(128) uint4 g_ahh[393216];   // w_hh fp16 hi
__device__ __align__(128) char g_bx[2][65536];   // B frags fp16 [x|h]
__device__ __align__(16) float g_cp[Tt * 64 * Bb]; // c partials [t][m][b]
__device__ __align__(16) float g_vp[2][8][Hh];
__device__ __align__(16) float g_v1[Hh];
__device__ __align__(16) float g_v2[Hh];
__device__ __align__(16) float g_bias[NN];
__device__ int g_mask_nzv[Bb];
__device__ unsigned g_hcnt, g_xcnt;
__device__ unsigned g_hrel, g_xrel;

// ===================== prep kernels =====================
__global__ void prep_pack_b(const float* __restrict__ features,
                            const float* __restrict__ b_ih,
                            const float* __restrict__ b_hh,
                            const float* __restrict__ mask) {
    int b = blockIdx.x, tid = threadIdx.x;
    int lane = tid & 31, wid = tid >> 5;
    if (b == 0 && tid == 0) { g_hcnt = 0u; g_xcnt = 0u; g_hrel = 0u; g_xrel = 0u; }
    int bi = b * 256 + tid;
    if (bi < N3) g_bias[bi] = b_ih[bi];
    else if (bi < NN) g_bias[bi] = b_hh[bi - N3];
    __shared__ unsigned wnz[8];
    float m0 = mask[b * Ss + tid], m1 = mask[b * Ss + tid + 256];
    unsigned bal = __ballot_sync(0xFFFFFFFFu, (m0 != 0.f) || (m1 != 0.f));
    if (lane == 0) wnz[wid] = bal;
    __syncthreads();
    if (tid == 0) {
        unsigned o = 0;
#pragma unroll
        for (int i = 0; i < 8; i++) o |= wnz[i];
        g_mask_nzv[b] = (o != 0u);
    }
#pragma unroll
    for (int jj = 0; jj < 4; jj++) {
        int j = tid + jj * 256;
        float v = features[b * Hh + j];
        uint32_t off = bx_off(j, b);
        *(unsigned short*)(g_bx[0] + off) = __half_as_ushort(__float2half_rn(v));
        *(unsigned short*)(g_bx[1] + off) = 0;
    }
}

__global__ void prep_v(const float* __restrict__ W1, const float* __restrict__ W2,
                       const float* __restrict__ V) {
    int hc = blockIdx.x, sel = blockIdx.y, tid = threadIdx.x;
    const float* W = sel ? W2 : W1;
    __shared__ float vs[128];
    if (tid < 128) vs[tid] = V[hc * 128 + tid];
    __syncthreads();
    float acc[4] = {0.f, 0.f, 0.f, 0.f};
    for (int h = 0; h < 128; h++) {
        const float* row = W + (size_t)(hc * 128 + h) * Hh;
        float vh = vs[h];
#pragma unroll
        for (int q = 0; q < 4; q++) acc[q] = fmaf(vh, row[tid + q * 256], acc[q]);
    }
#pragma unroll
    for (int q = 0; q < 4; q++) g_vp[sel][hc][tid + q * 256] = acc[q];
}

__global__ void prep_vred() {
    int i = blockIdx.x * 256 + threadIdx.x;
    int sel = i >> 10, d = i & 1023;
    float s = 0.f;
#pragma unroll
    for (int hc = 0; hc < 8; hc++) s += g_vp[sel][hc][d];
    if (sel) g_v2[d] = s; else g_v1[d] = s;
}

// pack W rows: slice m, warp (wm,kq) -> gate wm, rows m*16+jl, K-quarter kq
__global__ void prep_wfr(const float* __restrict__ w_ih, const float* __restrict__ w_hh) {
    int idx = blockIdx.x * 256 + threadIdx.x;   // 393216
    int lane = idx & 31;
    int p = (idx >> 5) & 15;
    int rest = idx >> 9;                         // 0..767
    int wid = rest % 12;
    int m = rest / 12;
    int wm = wid >> 2, kq = wid & 3;
    int gq = lane >> 2, tq = lane & 3;
    int k0 = kq * 256 + p * 16 + 2 * tq;

    int jl[2] = {gq, gq + 8};
    float vx[8], vh4[8];
#pragma unroll
    for (int rr = 0; rr < 2; rr++) {
        int Wrow = wm * 1024 + m * 16 + jl[rr];
        const float* Xr = w_ih + (size_t)Wrow * Hh;
        const float* Hr = w_hh + (size_t)Wrow * Hh;
        vx[rr * 2 + 0] = Xr[k0];     vx[rr * 2 + 1] = Xr[k0 + 1];
        vx[rr * 2 + 4] = Xr[k0 + 8]; vx[rr * 2 + 5] = Xr[k0 + 9];
        vh4[rr * 2 + 0] = Hr[k0];     vh4[rr * 2 + 1] = Hr[k0 + 1];
        vh4[rr * 2 + 4] = Hr[k0 + 8]; vh4[rr * 2 + 5] = Hr[k0 + 9];
    }
    uint32_t xh[4], xl[4], hh[4];
#pragma unroll
    for (int i = 0; i < 4; i++) {
        float a = vx[2 * i], b = vx[2 * i + 1];
        __half ha = __float2half_rn(a), hb = __float2half_rn(b);
        __half la = __float2half_rn((a - __half2float(ha)) * 4096.f);
        __half lb = __float2half_rn((b - __half2float(hb)) * 4096.f);
        xh[i] = pack_h2(ha, hb);
        xl[i] = pack_h2(la, lb);
        hh[i] = pack_h2(__float2half_rn(vh4[2 * i]), __float2half_rn(vh4[2 * i + 1]));
    }
    g_axh[idx] = make_uint4(xh[0], xh[1], xh[2], xh[3]);
    g_axl[idx] = make_uint4(xl[0], xl[1], xl[2], xl[3]);
    g_ahh[idx] = make_uint4(hh[0], hh[1], hh[2], hh[3]);
}

// ===================== persistent kernel =====================
extern __shared__ char dsm[];

// stage own batch-half columns (32KB compacted: 64 kc x 512B)
__device__ __forceinline__ void stageB(const char* __restrict__ src, int bh, int tid) {
    uint32_t sb = smem_u32(dsm);
    for (int i = tid; i < 2048; i += THREADS) {
        int kc = i >> 5, ch = i & 31;
        asm volatile("cp.async.cg.shared.global [%0], [%1], 16;"
            :: "r"(sb + i * 16),
               "l"(__cvta_generic_to_global(src + kc * 1024 + bh * 512 + ch * 16)) : "memory");
    }
    asm volatile("cp.async.commit_group;" ::: "memory");
    asm volatile("cp.async.wait_group 0;" ::: "memory");
    __syncthreads();
}

__global__ void __launch_bounds__(THREADS, 1)
gru_persist(const float* __restrict__ inputs, const float* __restrict__ mask,
            float* __restrict__ probs, float* __restrict__ ctx) {
    const int c = blockIdx.x;            // 0..143
    const int tid = threadIdx.x;
    const int wid = tid >> 5;
    const int lane = tid & 31;

    // ================= scorer CTAs (2 batches each) =================
    if (c >= NGEMM) {
        const int pb = (c - NGEMM) * 2;  // first batch of the pair
        float* sa  = (float*)dsm;               // [2][512]
        float* v2s = (float*)(dsm + 4096);
        float* p   = (float*)(dsm + 8192);      // 512 f
        float* red2 = (float*)(dsm + 10240);
        int*   si2  = (int*)(dsm + 10496);
        int*   sfl  = (int*)(dsm + 10752);

        if (tid == 0) {
            int nz = 0;
#pragma unroll
            for (int i = 0; i < Bb; i++) nz |= g_mask_nzv[i];
            sfl[0] = nz;
        }
        for (int i = tid; i < Hh; i += THREADS) v2s[i] = g_v2[i];
        __syncthreads();
        const bool mask_nz = (sfl[0] != 0);

        // a for both batches
#pragma unroll
        for (int bi = 0; bi < 2; bi++) {
            int b2 = pb + bi;
            for (int row = wid; row < Ss; row += 12) {
                const float* r = inputs + ((size_t)b2 * Ss + row) * Hh;
                float acc = 0.f;
#pragma unroll
                for (int i = 0; i < 8; i++) {
                    float4 x4 = *(const float4*)&r[(i * 32 + lane) * 4];
                    float4 v4 = *(const float4*)&v2s[(i * 32 + lane) * 4];
                    acc += x4.x * v4.x + x4.y * v4.y + x4.z * v4.z + x4.w * v4.w;
                }
#pragma unroll
                for (int o = 16; o > 0; o >>= 1) acc += __shfl_xor_sync(0xFFFFFFFFu, acc, o);
                if (lane == 0) sa[bi * 512 + row] = acc;
            }
        }
        __syncthreads();

        for (int t = 0; t < Tt; t++) {
            if (tid == 0) { while (ld_acquire(&g_hrel) < (unsigned)(t + 1)) { } }
            __syncthreads();
            // c for both batches in parallel: tid<128
            if (tid < 128) {
                int bi = tid >> 6, idx = tid & 63;
                float v = g_cp[(t * 64 + idx) * Bb + pb + bi];
#pragma unroll
                for (int o = 16; o > 0; o >>= 1) v += __shfl_xor_sync(0xFFFFFFFFu, v, o);
                if (lane == 0) red2[wid] = v;
            }
            __syncthreads();
            const float cA = red2[0] + red2[1];
            const float cB = red2[2] + red2[3];
#pragma unroll
            for (int bi = 0; bi < 2; bi++) {
                const int b2 = pb + bi;
                const float c0v = bi ? cB : cA;
                float s0 = 0.f, s1 = 0.f;
                if (tid < 256) {
                    s0 = ftanh(c0v + sa[bi * 512 + tid]);
                    s1 = ftanh(c0v + sa[bi * 512 + tid + 256]);
                    float* pr = probs + ((size_t)b2 * Tt + t) * Ss;
                    pr[tid] = s0;
                    pr[tid + 256] = s1;
                }
                if (t == 0 || mask_nz) {
                    if (tid < 256) {
                        float m0 = s0 + mask[b2 * Ss + tid];
                        float m1 = s1 + mask[b2 * Ss + tid + 256];
                        float bv = m0; int bi2 = tid;
                        if (m1 > bv) { bv = m1; bi2 = tid + 256; }
#pragma unroll
                        for (int o = 16; o > 0; o >>= 1) {
                            float v = __shfl_xor_sync(0xFFFFFFFFu, bv, o);
                            int ii = __shfl_xor_sync(0xFFFFFFFFu, bi2, o);
                            if (v > bv || (v == bv && ii < bi2)) { bv = v; bi2 = ii; }
                        }
                        if (lane == 0) { red2[8 + wid] = bv; si2[wid] = bi2; }
                    }
                    __syncthreads();
                    if (tid == 0) {
                        float v = red2[8]; int ii = si2[0];
#pragma unroll
                        for (int i = 1; i < 8; i++) {
                            float v2 = red2[8 + i]; int i2 = si2[i];
                            if (v2 > v || (v2 == v && i2 < ii)) { v = v2; ii = i2; }
                        }
                        si2[15] = ii;
                    }
                    __syncthreads();
                    int idx = si2[15];
                    const float* xr = inputs + ((size_t)b2 * Ss + idx) * Hh;
                    for (int k2 = tid; k2 < Hh; k2 += THREADS) {
                        *(unsigned short*)(g_bx[0] + bx_off(k2, b2)) =
                            __half_as_ushort(__float2half_rn(xr[k2]));
                    }
                    __syncthreads();
                }
            }
            if (t == 0 || mask_nz) {
                if (tid == 0) {
                    unsigned prev = atom_add_acqrel(&g_xcnt, 1u);
                    if ((prev & 15u) == 15u) st_release(&g_xrel, (unsigned)(t + 1));
                }
            }
            if (t == 0) {
                // ctx for both batches (overlapped with remaining steps)
#pragma unroll
                for (int bi = 0; bi < 2; bi++) {
                    const int b2 = pb + bi;
                    for (int s = tid; s < Ss; s += THREADS)
                        p[s] = probs[(size_t)b2 * Tt * Ss + s] + mask[b2 * Ss + s];
                    __syncthreads();
                    if (tid < 256) {
                        float m = fmaxf(p[tid], p[tid + 256]);
#pragma unroll
                        for (int o = 16; o > 0; o >>= 1) m = fmaxf(m, __shfl_xor_sync(0xFFFFFFFFu, m, o));
                        if (lane == 0) red2[16 + wid] = m;
                    }
                    __syncthreads();
                    if (tid == 0) {
                        float mm = red2[16];
#pragma unroll
                        for (int i = 1; i < 8; i++) mm = fmaxf(mm, red2[16 + i]);
                        red2[24] = mm;
                    }
                    __syncthreads();
                    const float mx = red2[24];
                    float sm = 0.f;
                    if (tid < 256) {
                        float e0 = __expf(p[tid] - mx), e1 = __expf(p[tid + 256] - mx);
                        p[tid] = e0; p[tid + 256] = e1;
                        sm = e0 + e1;
#pragma unroll
                        for (int o = 16; o > 0; o >>= 1) sm += __shfl_xor_sync(0xFFFFFFFFu, sm, o);
                        if (lane == 0) red2[32 + wid] = sm;
                    }
                    __syncthreads();
                    if (tid == 0) {
                        float ss = 0.f;
#pragma unroll
                        for (int i = 0; i < 8; i++) ss += red2[32 + i];
                        red2[40] = ss;
                    }
                    __syncthreads();
                    const float Z = red2[40];
                    if (tid < 256) {
                        float acc[4] = {0.f, 0.f, 0.f, 0.f};
                        for (int s = 0; s < Ss; s++) {
                            const float* row = inputs + ((size_t)b2 * Ss + s) * Hh;
                            float ps = p[s];
#pragma unroll
                            for (int q = 0; q < 4; q++) acc[q] = fmaf(ps, row[tid + q * 256], acc[q]);
                        }
#pragma unroll
                        for (int q = 0; q < 4; q++) ctx[b2 * Hh + tid + q * 256] = acc[q] / Z;
                    }
                    __syncthreads();
                }
            }
        }
        return;
    }

    // ================= GEMM + fused-update CTAs =================
    const int m = c >> 1;                // h-slice 0..63
    const int bh = c & 1;                // batch half
    const int kq = wid & 3;              // K-quarter

    float* yq   = (float*)(dsm + SM_Y);          // [kq][48][16]
    float* gxs  = (float*)(dsm + SM_GX);         // [48][16]
    float* hold = (float*)(dsm + SM_HOLD);       // [16][16]
    float* brS  = (float*)(dsm + SM_BIAS);
    float* bzS  = brS + 16;
    float* bniS = brS + 32;
    float* bnhS = brS + 48;
    float* v1S  = brS + 64;
    float* c256 = (float*)(dsm + SM_C256);
    int*   sfl  = (int*)(dsm + SM_FLG);

    if (tid == 0) {
        int nz = 0;
#pragma unroll
        for (int i = 0; i < Bb; i++) nz |= g_mask_nzv[i];
        sfl[0] = nz;
    }
    if (tid < 16) {
        int jg = m * 16 + tid;
        brS[tid] = g_bias[jg] + g_bias[3072 + jg];
        bzS[tid] = g_bias[1024 + jg] + g_bias[4096 + jg];
        bniS[tid] = g_bias[2048 + jg];
        bnhS[tid] = g_bias[5120 + jg];
        v1S[tid] = g_v1[jg];
    }
    for (int i = tid; i < 256; i += THREADS) hold[i] = 0.f;
    __syncthreads();
    const bool mask_nz = (sfl[0] != 0);

    const size_t abase = ((size_t)(m * 12 + wid)) * 512;   // [m][wid][p][lane]
    const uint4* Axh = g_axh + abase;
    const uint4* Axl = g_axl + abase;
    const uint4* Ahh = g_ahh + abase;
    float* ybW = yq + kq * 768;          // this K-quarter's buffer [48][16]
    const int wm = wid >> 2;
    const int r0 = wm * 16 + (lane >> 2);
    const int c0f = 2 * (lane & 3);

    for (int t = 0; t < Tt; t++) {
        const bool xp = (t <= 1) || mask_nz;
        const bool hp = (t >= 1);
        if (t >= 1) {
            if (tid == 0) {
                while (ld_acquire(&g_hrel) < (unsigned)t) { }
                if (xp) { while (ld_acquire(&g_xrel) < (unsigned)t) { } }
            }
            __syncthreads();
        }

        if (xp) {
            stageB(g_bx[0], bh, tid);
            float acch[2][4], accl[2][4];
#pragma unroll
            for (int i = 0; i < 2; i++)
#pragma unroll
                for (int j = 0; j < 4; j++) { acch[i][j] = 0.f; accl[i][j] = 0.f; }
            uint4 AH[4], AL[4];
#pragma unroll
            for (int p = 0; p < 3; p++) { AH[p] = Axh[p * 32 + lane]; AL[p] = Axl[p * 32 + lane]; }
#pragma unroll
            for (int p = 0; p < 16; p++) {
                const int s = p & 3;
                if (p + 3 < 16) {
                    const int q = (p + 3) & 3;
                    AH[q] = Axh[(p + 3) * 32 + lane];
                    AL[q] = Axl[(p + 3) * 32 + lane];
                }
                const char* bb = dsm + (kq * 16 + p) * 512 + lane * 8;
#pragma unroll
                for (int nn = 0; nn < 2; nn++) {
                    uint2 bv = *(const uint2*)(bb + nn * 256);
                    mma16816(acch[nn], &AH[s].x, bv.x, bv.y);
                    mma16816(accl[nn], &AL[s].x, bv.x, bv.y);
                }
            }
#pragma unroll
            for (int nn = 0; nn < 2; nn++) {
                int col = nn * 8 + c0f;
                ybW[r0 * 16 + col]           = acch[nn][0] + accl[nn][0] * (1.f / 4096.f);
                ybW[r0 * 16 + col + 1]       = acch[nn][1] + accl[nn][1] * (1.f / 4096.f);
                ybW[(r0 + 8) * 16 + col]     = acch[nn][2] + accl[nn][2] * (1.f / 4096.f);
                ybW[(r0 + 8) * 16 + col + 1] = acch[nn][3] + accl[nn][3] * (1.f / 4096.f);
            }
            __syncthreads();
            for (int i = tid; i < 768; i += THREADS)
                gxs[i] = yq[i] + yq[768 + i] + yq[1536 + i] + yq[2304 + i];
            __syncthreads();
        }

        if (hp) {
            stageB(g_bx[1], bh, tid);
            float acch[2][4];
#pragma unroll
            for (int i = 0; i < 2; i++)
#pragma unroll
                for (int j = 0; j < 4; j++) acch[i][j] = 0.f;
            uint4 AH[4];
#pragma unroll
            for (int p = 0; p < 3; p++) AH[p] = Ahh[p * 32 + lane];
#pragma unroll
            for (int p = 0; p < 16; p++) {
                const int s = p & 3;
                if (p + 3 < 16) AH[(p + 3) & 3] = Ahh[(p + 3) * 32 + lane];
                const char* bb = dsm + (kq * 16 + p) * 512 + lane * 8;
#pragma unroll
                for (int nn = 0; nn < 2; nn++) {
                    uint2 bv = *(const uint2*)(bb + nn * 256);
                    mma16816(acch[nn], &AH[s].x, bv.x, bv.y);
                }
            }
#pragma unroll
            for (int nn = 0; nn < 2; nn++) {
                int col = nn * 8 + c0f;
                ybW[r0 * 16 + col]           = acch[nn][0];
                ybW[r0 * 16 + col + 1]       = acch[nn][1];
                ybW[(r0 + 8) * 16 + col]     = acch[nn][2];
                ybW[(r0 + 8) * 16 + col + 1] = acch[nn][3];
            }
            __syncthreads();
        }

        // ---- fused GRU update for h[m*16..+16) x batches[bh*16..+16) ----
        if (tid < 256) {
            int jl = tid >> 4, bl = tid & 15;
            float yr = 0.f, yz = 0.f, yn = 0.f;
            if (hp) {
                yr = yq[jl * 16 + bl]        + yq[768 + jl * 16 + bl]
                   + yq[1536 + jl * 16 + bl] + yq[2304 + jl * 16 + bl];
                yz = yq[(16 + jl) * 16 + bl]        + yq[768 + (16 + jl) * 16 + bl]
                   + yq[1536 + (16 + jl) * 16 + bl] + yq[2304 + (16 + jl) * 16 + bl];
                yn = yq[(32 + jl) * 16 + bl]        + yq[768 + (32 + jl) * 16 + bl]
                   + yq[1536 + (32 + jl) * 16 + bl] + yq[2304 + (32 + jl) * 16 + bl];
            }
            float r = fsigmoid(gxs[jl * 16 + bl] + yr + brS[jl]);
            float z = fsigmoid(gxs[(16 + jl) * 16 + bl] + yz + bzS[jl]);
            float nv = ftanh(gxs[(32 + jl) * 16 + bl] + bniS[jl] + r * (yn + bnhS[jl]));
            float hnew = (1.f - z) * nv + z * hold[tid];
            hold[tid] = hnew;
            *(unsigned short*)(g_bx[1] + bx_off(m * 16 + jl, bh * 16 + bl)) =
                __half_as_ushort(__float2half_rn(hnew));
            c256[tid] = v1S[jl] * hnew;
        }
        __syncthreads();
        if (tid < 16) {
            float s = 0.f;
#pragma unroll
            for (int jl = 0; jl < 16; jl++) s += c256[jl * 16 + tid];
            g_cp[(t * 64 + m) * Bb + bh * 16 + tid] = s;
        }
        __syncthreads();
        if (tid == 0) {
            unsigned prev = atom_add_acqrel(&g_hcnt, 1u);
            if ((prev & 127u) == 127u) st_release(&g_hrel, (unsigned)(t + 1));
        }
    }
}

// ===================== launch =====================
extern "C" void kernel_launch(void* const* d_in, const int* in_sizes, int n_in,
                              void* d_out, int out_size) {
    const float* inputs   = (const float*)d_in[0];
    const float* mask     = (const float*)d_in[1];
    // d_in[2] = inputs_embeds (unused, use_emb=False)
    const float* features = (const float*)d_in[3];
    const float* w_ih     = (const float*)d_in[4];
    const float* b_ih     = (const float*)d_in[5];
    const float* w_hh     = (const float*)d_in[6];
    const float* b_hh     = (const float*)d_in[7];
    const float* W1       = (const float*)d_in[8];
    const float* W2       = (const float*)d_in[9];
    const float* V        = (const float*)d_in[10];

    float* out   = (float*)d_out;
    float* probs = out;                            // [B, T, S]
    float* ctx   = out + (size_t)Bb * Tt * Ss;     // [B, H]

    cudaFuncSetAttribute(gru_persist, cudaFuncAttributeMaxDynamicSharedMemorySize, DSMEM);

    prep_pack_b<<<Bb, 256>>>(features, b_ih, b_hh, mask);
    prep_v<<<dim3(8, 2), 256>>>(W1, W2, V);
    prep_vred<<<8, 256>>>();
    prep_wfr<<<1536, 256>>>(w_ih, w_hh);

    gru_persist<<<GRID, THREADS, DSMEM>>>(inputs, mask, probs, ctx);
}